// round 2
// baseline (speedup 1.0000x reference)
#include <cuda_runtime.h>
#include <cuda_bf16.h>

#define NB 128
#define NT 128
#define NC 32
#define NH 128
#define NO 10
#define NCTA 128
#define NTHR 256
#define MAXSTEPS 64
#define RTOL_ 1e-3f
#define ATOL_ 1e-3f

#define OFF_W1T 0
#define OFF_H1S (OFF_W1T + NH*NH)
#define OFF_W2S (OFF_H1S + NH*NB)
#define OFF_DXT (OFF_W2S + 32*NH)
#define OFF_RED (OFF_DXT + NC*NB)
#define OFF_TS  (OFF_RED + 16*NB)
#define OFF_B1  (OFF_TS + NT)
#define OFF_B2  (OFF_B1 + NH)
#define OFF_YS  (OFF_B2 + 32)
#define OFF_SC  (OFF_YS + NH)
#define SMEM_FLOATS (OFF_SC + 8)
#define SMEM_BYTES (SMEM_FLOATS * 4)

__device__ __align__(16) float g_Y[NB*NH];
__device__ __align__(16) float g_ynew[NB*NH];
__device__ __align__(16) float g_t[NB];
__device__ __align__(16) float g_dt[NB];
__device__ __align__(16) float g_k[7][NB*NH];
__device__ __align__(16) float g_H1[NH*NB];
__device__ __align__(16) float g_dX[NB*NC];
__device__ unsigned g_cnt;
__device__ unsigned g_gen;

__constant__ float A_TAB[7][6] = {
  {0.f,0.f,0.f,0.f,0.f,0.f},
  {(float)(1.0/5.0),0.f,0.f,0.f,0.f,0.f},
  {(float)(3.0/40.0),(float)(9.0/40.0),0.f,0.f,0.f,0.f},
  {(float)(44.0/45.0),(float)(-56.0/15.0),(float)(32.0/9.0),0.f,0.f,0.f},
  {(float)(19372.0/6561.0),(float)(-25360.0/2187.0),(float)(64448.0/6561.0),(float)(-212.0/729.0),0.f,0.f},
  {(float)(9017.0/3168.0),(float)(-355.0/33.0),(float)(46732.0/5247.0),(float)(49.0/176.0),(float)(-5103.0/18656.0),0.f},
  {(float)(35.0/384.0),0.f,(float)(500.0/1113.0),(float)(125.0/192.0),(float)(-2187.0/6784.0),(float)(11.0/84.0)},
};
__constant__ float C_TAB[7] = {0.f,(float)(1.0/5.0),(float)(3.0/10.0),(float)(4.0/5.0),(float)(8.0/9.0),1.f,1.f};

#define E0 ((float)(71.0/57600.0))
#define E2 ((float)(-71.0/16695.0))
#define E3 ((float)(71.0/1920.0))
#define E4 ((float)(-17253.0/339200.0))
#define E5 ((float)(22.0/525.0))
#define E6 ((float)(-1.0/40.0))

__device__ __forceinline__ unsigned long long fma2(unsigned long long a, unsigned long long b, unsigned long long c) {
  unsigned long long d;
  asm("fma.rn.f32x2 %0, %1, %2, %3;" : "=l"(d) : "l"(a), "l"(b), "l"(c));
  return d;
}
__device__ __forceinline__ unsigned long long pack2(float x, float y) {
  unsigned long long d; asm("mov.b64 %0, {%1, %2};" : "=l"(d) : "f"(x), "f"(y)); return d;
}
__device__ __forceinline__ void unpack2(unsigned long long v, float& x, float& y) {
  asm("mov.b64 {%0, %1}, %2;" : "=f"(x), "=f"(y) : "l"(v));
}
__device__ __forceinline__ unsigned ld_gen() {
  unsigned v;
  asm volatile("ld.global.cg.u32 %0, [%1];" : "=r"(v) : "l"(&g_gen));
  return v;
}

__device__ __forceinline__ void gbar() {
  __threadfence();
  __syncthreads();
  if (threadIdx.x == 0) {
    unsigned g0 = ld_gen();
    __threadfence();
    unsigned a = atomicAdd(&g_cnt, 1u);
    if (a == NCTA - 1) {
      atomicExch(&g_cnt, 0u);
      __threadfence();
      atomicExch(&g_gen, g0 + 1u);
    } else {
      while (ld_gen() == g0) __nanosleep(64);
    }
    __threadfence();
  }
  __syncthreads();
}

__global__ __launch_bounds__(NTHR, 1)
void cde_kernel(const float* __restrict__ ts, const float* __restrict__ xs,
                const float* __restrict__ W1, const float* __restrict__ b1,
                const float* __restrict__ W2, const float* __restrict__ b2,
                const float* __restrict__ lin_w, const float* __restrict__ lin_b,
                float* __restrict__ out)
{
  extern __shared__ float sm[];
  float* W1T = sm + OFF_W1T;
  float* H1s = sm + OFF_H1S;
  float* W2s = sm + OFF_W2S;
  float* dXT = sm + OFF_DXT;
  float* red = sm + OFF_RED;
  float* tss = sm + OFF_TS;
  float* b1s = sm + OFF_B1;
  float* b2s = sm + OFF_B2;
  float* Ysm = sm + OFF_YS;
  float* scal= sm + OFF_SC;

  const int tid = threadIdx.x;
  const int bid = blockIdx.x;

  for (int i = tid; i < NH*NH; i += NTHR) { int h = i >> 7, k = i & 127; W1T[k*NH + h] = W1[i]; }
  for (int i = tid; i < 32*NH; i += NTHR) W2s[i] = W2[bid*32*NH + i];
  for (int i = tid; i < NT; i += NTHR) tss[i] = ts[i];
  for (int i = tid; i < NH; i += NTHR) b1s[i] = b1[i];
  if (tid < 32) b2s[tid] = b2[bid*32 + tid];
  if (tid < NH) g_Y[bid*NH + tid] = 0.f;
  if (tid == 0) { g_t[bid] = ts[0]; g_dt[bid] = 0.01f; }
  __syncthreads();
  const float tEnd = tss[NT-1];
  const float* xb = xs + (size_t)bid*NT*NC;

  for (int step = 0; step < MAXSTEPS; step++) {
    for (int s = 0; s < 7; s++) {
      // ---- phase A : CTA = batch ----
      if (tid == 0) {
        float t = g_t[bid], dtv = g_dt[bid];
        float dt_c = fminf(dtv, tEnd - t);
        scal[0] = t; scal[1] = dtv; scal[2] = dt_c;
      }
      __syncthreads();
      const float tcur = scal[0];
      const float dt_c = scal[2];
      if (tid < NH) {
        float y = g_Y[bid*NH + tid];
        float ysv;
        if (s == 0) ysv = y;
        else {
          float acc = 0.f;
          for (int j = 0; j < s; j++)
            acc += A_TAB[s][j] * __ldcg(&g_k[j][bid*NH + tid]);
          ysv = y + dt_c * acc;
        }
        Ysm[tid] = ysv;
        if (s == 6) g_ynew[bid*NH + tid] = ysv;
      } else if (tid < NH + NC) {
        int c = tid - NH;
        float tq = tcur + C_TAB[s] * dt_c;
        int lo = 0, hi = NT;
        while (lo < hi) { int mid = (lo + hi) >> 1; if (tss[mid] <= tq) lo = mid + 1; else hi = mid; }
        int idx = lo - 1; if (idx < 0) idx = 0; if (idx > NT-2) idx = NT-2;
        float t0 = tss[idx], t1 = tss[idx+1];
        float hh = t1 - t0;
        float sfr = (tq - t0) / hh;
        float dh00 = 6.f*sfr*sfr - 6.f*sfr;
        float dh10 = 3.f*sfr*sfr - 4.f*sfr + 1.f;
        float dh11 = 3.f*sfr*sfr - 2.f*sfr;
        float x0 = __ldg(&xb[idx*NC + c]);
        float x1 = __ldg(&xb[(idx+1)*NC + c]);
        float mi1 = (x1 - x0) / hh;
        float mi;
        if (idx == 0) mi = (x1 - x0) / (tss[1] - tss[0]);
        else { float xm1 = __ldg(&xb[(idx-1)*NC + c]); mi = (x0 - xm1) / (tss[idx] - tss[idx-1]); }
        float dx = (dh00*x0 - dh00*x1) / hh + dh10*mi + dh11*mi1;
        __stcg(&g_dX[bid*NC + c], dx);
      }
      __syncthreads();
      if (tid < NH) {
        float a0=0.f,a1=0.f,a2=0.f,a3=0.f;
        #pragma unroll 8
        for (int k = 0; k < NH; k += 4) {
          a0 = fmaf(W1T[(k  )*NH + tid], Ysm[k  ], a0);
          a1 = fmaf(W1T[(k+1)*NH + tid], Ysm[k+1], a1);
          a2 = fmaf(W1T[(k+2)*NH + tid], Ysm[k+2], a2);
          a3 = fmaf(W1T[(k+3)*NH + tid], Ysm[k+3], a3);
        }
        float h1 = fmaxf(b1s[tid] + ((a0+a1)+(a2+a3)), 0.f);
        __stcg(&g_H1[tid*NB + bid], h1);
      }
      gbar();

      // ---- phase B : CTA = hidden unit ----
      {
        const float4* src = (const float4*)g_H1;
        for (int i = tid; i < (NH*NB)/4; i += NTHR)
          ((float4*)H1s)[i] = __ldcg(src + i);
        for (int i = tid; i < NB*NC; i += NTHR) {
          int b = i >> 5, c = i & 31;
          dXT[c*NB + b] = __ldcg(&g_dX[i]);
        }
        __syncthreads();

        const int cp = tid >> 4;
        const int bo = tid & 15;
        const int c0 = cp * 2;
        const int b0 = bo * 8;
        float dxr0[8], dxr1[8];
        #pragma unroll
        for (int j = 0; j < 8; j++) {
          dxr0[j] = dXT[c0*NB + b0 + j];
          dxr1[j] = dXT[(c0+1)*NB + b0 + j];
        }
        unsigned long long ac[2][4];
        #pragma unroll
        for (int i = 0; i < 2; i++)
          #pragma unroll
          for (int p = 0; p < 4; p++) ac[i][p] = pack2(0.f, 0.f);

        #pragma unroll 4
        for (int h = 0; h < NH; h++) {
          float a0 = W2s[c0*NH + h];
          float a1 = W2s[(c0+1)*NH + h];
          unsigned long long A0 = pack2(a0, a0);
          unsigned long long A1 = pack2(a1, a1);
          const ulonglong2* hp = (const ulonglong2*)&H1s[h*NB + b0];
          ulonglong2 u0 = hp[0];
          ulonglong2 u1 = hp[1];
          ac[0][0] = fma2(A0, u0.x, ac[0][0]);
          ac[0][1] = fma2(A0, u0.y, ac[0][1]);
          ac[0][2] = fma2(A0, u1.x, ac[0][2]);
          ac[0][3] = fma2(A0, u1.y, ac[0][3]);
          ac[1][0] = fma2(A1, u0.x, ac[1][0]);
          ac[1][1] = fma2(A1, u0.y, ac[1][1]);
          ac[1][2] = fma2(A1, u1.x, ac[1][2]);
          ac[1][3] = fma2(A1, u1.y, ac[1][3]);
        }
        float part[8];
        #pragma unroll
        for (int j = 0; j < 8; j++) part[j] = 0.f;
        #pragma unroll
        for (int i = 0; i < 2; i++) {
          float bb = b2s[c0 + i];
          const float* dxr = i ? dxr1 : dxr0;
          #pragma unroll
          for (int p = 0; p < 4; p++) {
            float d0, d1; unpack2(ac[i][p], d0, d1);
            part[2*p]   += tanhf(d0 + bb) * dxr[2*p];
            part[2*p+1] += tanhf(d1 + bb) * dxr[2*p+1];
          }
        }
        #pragma unroll
        for (int j = 0; j < 8; j++) red[cp*NB + b0 + j] = part[j];
        __syncthreads();
        if (tid < NB) {
          float kv = 0.f;
          #pragma unroll
          for (int q = 0; q < 16; q++) kv += red[q*NB + tid];
          __stcg(&g_k[s][tid*NH + bid], kv);
        }
      }
      gbar();
    }

    // ---- phase C : accept/reject (CTA = batch) ----
    {
      const float t = scal[0], dtv = scal[1], dt_c = scal[2];
      if (tid < NH) {
        int h = tid;
        float k1 = __ldcg(&g_k[0][bid*NH+h]);
        float k3 = __ldcg(&g_k[2][bid*NH+h]);
        float k4 = __ldcg(&g_k[3][bid*NH+h]);
        float k5 = __ldcg(&g_k[4][bid*NH+h]);
        float k6 = __ldcg(&g_k[5][bid*NH+h]);
        float k7 = __ldcg(&g_k[6][bid*NH+h]);
        float y  = g_Y[bid*NH+h];
        float yn = g_ynew[bid*NH+h];
        float ev = dt_c * (E0*k1 + E2*k3 + E3*k4 + E4*k5 + E5*k6 + E6*k7);
        float sc = ATOL_ + RTOL_ * fmaxf(fabsf(y), fabsf(yn));
        float e = ev / sc;
        float e2v = e*e;
        #pragma unroll
        for (int o = 16; o > 0; o >>= 1) e2v += __shfl_down_sync(0xffffffffu, e2v, o);
        if ((tid & 31) == 0) red[tid >> 5] = e2v;
      }
      __syncthreads();
      if (tid == 0) {
        float ssum = red[0] + red[1] + red[2] + red[3];
        float err = sqrtf(ssum * (1.f/(float)NH));
        bool accept = (err <= 1.0f);
        float fac = 0.9f * powf(fmaxf(err, 1e-9f), -0.2f);
        fac = fminf(fmaxf(fac, 0.2f), 10.f);
        bool done = (t >= tEnd - 1e-8f);
        bool adv = accept && !done;
        g_t[bid]  = adv ? (t + dt_c) : t;
        g_dt[bid] = done ? dtv : (dt_c * fac);
        scal[3] = adv ? 1.f : 0.f;
      }
      __syncthreads();
      if (tid < NH && scal[3] != 0.f) g_Y[bid*NH + tid] = g_ynew[bid*NH + tid];
      __syncthreads();
    }
  }

  if (tid < NO) {
    float acc = lin_b[tid];
    #pragma unroll 4
    for (int h = 0; h < NH; h++)
      acc = fmaf(lin_w[tid*NH + h], g_Y[bid*NH + h], acc);
    out[bid*NO + tid] = acc;
  }
}

extern "C" void kernel_launch(void* const* d_in, const int* in_sizes, int n_in,
                              void* d_out, int out_size) {
  const float* ts    = (const float*)d_in[0];
  const float* xs    = (const float*)d_in[1];
  const float* W1    = (const float*)d_in[2];
  const float* b1    = (const float*)d_in[3];
  const float* W2    = (const float*)d_in[4];
  const float* b2    = (const float*)d_in[5];
  const float* lin_w = (const float*)d_in[6];
  const float* lin_b = (const float*)d_in[7];
  float* out = (float*)d_out;
  cudaFuncSetAttribute(cde_kernel, cudaFuncAttributeMaxDynamicSharedMemorySize, SMEM_BYTES);
  cde_kernel<<<NCTA, NTHR, SMEM_BYTES>>>(ts, xs, W1, b1, W2, b2, lin_w, lin_b, out);
}

// round 3
// speedup vs baseline: 21.0895x; 21.0895x over previous
#include <cuda_runtime.h>

#define NB 128
#define NT 128
#define NC 32
#define NH 128
#define NO 10
#define NCTA 128
#define NTHR 256
#define MAXSTEPS 64
#define RTOL_ 1e-3f
#define ATOL_ 1e-3f
#define DXP 129   // padded dXT row stride (bank-conflict-free)

#define OFF_W1T 0
#define OFF_H1S (OFF_W1T + NH*NH)          // 16384
#define OFF_W2S (OFF_H1S + NH*NB)          // 32768
#define OFF_DXT (OFF_W2S + 32*NH)          // 36864
#define OFF_RED (OFF_DXT + NC*DXP)         // 40992
#define OFF_TS  (OFF_RED + 16*NB)          // 43040
#define OFF_B1  (OFF_TS + NT)              // 43168
#define OFF_B2  (OFF_B1 + NH)              // 43296
#define OFF_YS  (OFF_B2 + 32)              // 43328
#define OFF_SC  (OFF_YS + NH)              // 43456
#define SMEM_FLOATS (OFF_SC + 8)
#define SMEM_BYTES (SMEM_FLOATS * 4)

__device__ __align__(16) float g_Y[NB*NH];
__device__ __align__(16) float g_ynew[NB*NH];
__device__ __align__(16) float g_t[NB];
__device__ __align__(16) float g_dt[NB];
__device__ __align__(16) float g_k[7][NB*NH];
__device__ __align__(16) float g_H1[NH*NB];
__device__ __align__(16) float g_dX[NB*NC];
__device__ unsigned g_cnt;
__device__ unsigned g_gen;
__device__ unsigned g_ndone;

__constant__ float A_TAB[7][6] = {
  {0.f,0.f,0.f,0.f,0.f,0.f},
  {(float)(1.0/5.0),0.f,0.f,0.f,0.f,0.f},
  {(float)(3.0/40.0),(float)(9.0/40.0),0.f,0.f,0.f,0.f},
  {(float)(44.0/45.0),(float)(-56.0/15.0),(float)(32.0/9.0),0.f,0.f,0.f},
  {(float)(19372.0/6561.0),(float)(-25360.0/2187.0),(float)(64448.0/6561.0),(float)(-212.0/729.0),0.f,0.f},
  {(float)(9017.0/3168.0),(float)(-355.0/33.0),(float)(46732.0/5247.0),(float)(49.0/176.0),(float)(-5103.0/18656.0),0.f},
  {(float)(35.0/384.0),0.f,(float)(500.0/1113.0),(float)(125.0/192.0),(float)(-2187.0/6784.0),(float)(11.0/84.0)},
};
__constant__ float C_TAB[7] = {0.f,(float)(1.0/5.0),(float)(3.0/10.0),(float)(4.0/5.0),(float)(8.0/9.0),1.f,1.f};

#define E0 ((float)(71.0/57600.0))
#define E2 ((float)(-71.0/16695.0))
#define E3 ((float)(71.0/1920.0))
#define E4 ((float)(-17253.0/339200.0))
#define E5 ((float)(22.0/525.0))
#define E6 ((float)(-1.0/40.0))

__device__ __forceinline__ unsigned long long fma2(unsigned long long a, unsigned long long b, unsigned long long c) {
  unsigned long long d;
  asm("fma.rn.f32x2 %0, %1, %2, %3;" : "=l"(d) : "l"(a), "l"(b), "l"(c));
  return d;
}
__device__ __forceinline__ unsigned long long pack2(float x, float y) {
  unsigned long long d; asm("mov.b64 %0, {%1, %2};" : "=l"(d) : "f"(x), "f"(y)); return d;
}
__device__ __forceinline__ void unpack2(unsigned long long v, float& x, float& y) {
  asm("mov.b64 {%0, %1}, %2;" : "=f"(x), "=f"(y) : "l"(v));
}
__device__ __forceinline__ unsigned ld_u32_cg(const unsigned* p) {
  unsigned v;
  asm volatile("ld.global.cg.u32 %0, [%1];" : "=r"(v) : "l"(p));
  return v;
}
__device__ __forceinline__ float fast_tanh(float x) {
  x = fminf(fmaxf(x, -9.f), 9.f);
  float e = __expf(2.f * x);
  return __fdividef(e - 1.f, e + 1.f);
}

// tight-poll generation barrier; all 128 CTAs co-resident (1/SM)
__device__ __forceinline__ void gbar() {
  __syncthreads();
  if (threadIdx.x == 0) {
    __threadfence();
    unsigned g0 = ld_u32_cg(&g_gen);
    unsigned a = atomicAdd(&g_cnt, 1u);
    if (a == NCTA - 1) {
      atomicExch(&g_cnt, 0u);
      __threadfence();
      atomicExch(&g_gen, g0 + 1u);
    } else {
      while (ld_u32_cg(&g_gen) == g0) { }
    }
    __threadfence();
  }
  __syncthreads();
}

__global__ __launch_bounds__(NTHR, 1)
void cde_kernel(const float* __restrict__ ts, const float* __restrict__ xs,
                const float* __restrict__ W1, const float* __restrict__ b1,
                const float* __restrict__ W2, const float* __restrict__ b2,
                const float* __restrict__ lin_w, const float* __restrict__ lin_b,
                float* __restrict__ out)
{
  extern __shared__ float sm[];
  float* W1T = sm + OFF_W1T;
  float* H1s = sm + OFF_H1S;
  float* W2s = sm + OFF_W2S;
  float* dXT = sm + OFF_DXT;
  float* red = sm + OFF_RED;
  float* tss = sm + OFF_TS;
  float* b1s = sm + OFF_B1;
  float* b2s = sm + OFF_B2;
  float* Ysm = sm + OFF_YS;
  float* scal= sm + OFF_SC;

  const int tid = threadIdx.x;
  const int bid = blockIdx.x;

  for (int i = tid; i < NH*NH; i += NTHR) { int h = i >> 7, k = i & 127; W1T[k*NH + h] = W1[i]; }
  for (int i = tid; i < 32*NH; i += NTHR) W2s[i] = W2[bid*32*NH + i];
  for (int i = tid; i < NT; i += NTHR) tss[i] = ts[i];
  for (int i = tid; i < NH; i += NTHR) b1s[i] = b1[i];
  if (tid < 32) b2s[tid] = b2[bid*32 + tid];
  if (tid < NH) g_Y[bid*NH + tid] = 0.f;
  if (tid == 0) {
    g_t[bid] = ts[0]; g_dt[bid] = 0.01f;
    if (bid == 0) atomicExch(&g_ndone, 0u);   // replay-safe reset before first gbar
  }
  __syncthreads();
  const float tEnd = tss[NT-1];
  const float* xb = xs + (size_t)bid*NT*NC;

  bool counted = false;      // thread-0-only meaning
  bool exit_all = false;

  for (int step = 0; step < MAXSTEPS && !exit_all; step++) {
    for (int s = 0; s < 7; s++) {
      // ======== phase A : CTA = batch ========
      if (tid == 0) {
        float t = g_t[bid], dtv = g_dt[bid];
        float dt_c = fminf(dtv, tEnd - t);
        scal[0] = t; scal[1] = dtv; scal[2] = dt_c;
      }
      __syncthreads();
      const float tcur = scal[0];
      const float dt_c = scal[2];
      if (tid < NH) {
        float y = g_Y[bid*NH + tid];
        float ysv;
        if (s == 0) ysv = y;
        else {
          float acc = 0.f;
          for (int j = 0; j < s; j++)
            acc += A_TAB[s][j] * __ldcg(&g_k[j][bid*NH + tid]);
          ysv = y + dt_c * acc;
        }
        Ysm[tid] = ysv;
        if (s == 6) g_ynew[bid*NH + tid] = ysv;
      } else if (tid < NH + NC) {
        int c = tid - NH;
        float tq = tcur + C_TAB[s] * dt_c;
        int lo = 0, hi = NT;
        while (lo < hi) { int mid = (lo + hi) >> 1; if (tss[mid] <= tq) lo = mid + 1; else hi = mid; }
        int idx = lo - 1; if (idx < 0) idx = 0; if (idx > NT-2) idx = NT-2;
        float t0 = tss[idx], t1 = tss[idx+1];
        float hh = t1 - t0;
        float sfr = (tq - t0) / hh;
        float dh00 = 6.f*sfr*sfr - 6.f*sfr;
        float dh10 = 3.f*sfr*sfr - 4.f*sfr + 1.f;
        float dh11 = 3.f*sfr*sfr - 2.f*sfr;
        float x0 = __ldg(&xb[idx*NC + c]);
        float x1 = __ldg(&xb[(idx+1)*NC + c]);
        float mi1 = (x1 - x0) / hh;
        float mi;
        if (idx == 0) mi = (x1 - x0) / (tss[1] - tss[0]);
        else { float xm1 = __ldg(&xb[(idx-1)*NC + c]); mi = (x0 - xm1) / (tss[idx] - tss[idx-1]); }
        float dx = (dh00*x0 - dh00*x1) / hh + dh10*mi + dh11*mi1;
        __stcg(&g_dX[bid*NC + c], dx);
      }
      __syncthreads();
      // W1 matvec on all 8 warps: split-k halves
      {
        int h = tid & 127;
        int half = tid >> 7;
        const int kb = half * 64;
        float a0=0.f,a1=0.f,a2=0.f,a3=0.f;
        #pragma unroll 4
        for (int k = 0; k < 64; k += 4) {
          float4 yv = *(const float4*)&Ysm[kb + k];
          a0 = fmaf(W1T[(kb+k  )*NH + h], yv.x, a0);
          a1 = fmaf(W1T[(kb+k+1)*NH + h], yv.y, a1);
          a2 = fmaf(W1T[(kb+k+2)*NH + h], yv.z, a2);
          a3 = fmaf(W1T[(kb+k+3)*NH + h], yv.w, a3);
        }
        red[half*NH + h] = (a0+a1)+(a2+a3);
      }
      __syncthreads();
      if (tid < NH) {
        float h1 = fmaxf(b1s[tid] + red[tid] + red[NH + tid], 0.f);
        __stcg(&g_H1[tid*NB + bid], h1);
      }
      gbar();

      // early-exit check at a barrier-consistent point (once per step)
      if (s == 0) {
        if (tid == 0) scal[4] = (float)ld_u32_cg(&g_ndone);
        __syncthreads();
        if (scal[4] == (float)NB) { exit_all = true; break; }
      }

      // ======== phase B : CTA = hidden unit ========
      {
        const float4* src = (const float4*)g_H1;
        for (int i = tid; i < (NH*NB)/4; i += NTHR)
          ((float4*)H1s)[i] = __ldcg(src + i);
        for (int i = tid; i < NB*NC; i += NTHR) {
          int c = i & 31, b = i >> 5;
          dXT[c*DXP + b] = __ldcg(&g_dX[b*NC + c]);
        }
        __syncthreads();

        const int cp = tid >> 4;      // 0..15
        const int bo = tid & 15;      // 0..15
        const int c0 = cp * 2;
        const int b0 = bo * 8;
        float dxr0[8], dxr1[8];
        #pragma unroll
        for (int j = 0; j < 8; j++) {
          dxr0[j] = dXT[c0*DXP + b0 + j];
          dxr1[j] = dXT[(c0+1)*DXP + b0 + j];
        }
        unsigned long long ac[2][4];
        #pragma unroll
        for (int i = 0; i < 2; i++)
          #pragma unroll
          for (int p = 0; p < 4; p++) ac[i][p] = pack2(0.f, 0.f);

        #pragma unroll 2
        for (int hc = 0; hc < NH; hc += 8) {
          float4 wa0 = *(const float4*)&W2s[c0*NH + hc];
          float4 wa1 = *(const float4*)&W2s[c0*NH + hc + 4];
          float4 wb0 = *(const float4*)&W2s[(c0+1)*NH + hc];
          float4 wb1 = *(const float4*)&W2s[(c0+1)*NH + hc + 4];
          const float wA[8] = {wa0.x,wa0.y,wa0.z,wa0.w,wa1.x,wa1.y,wa1.z,wa1.w};
          const float wB[8] = {wb0.x,wb0.y,wb0.z,wb0.w,wb1.x,wb1.y,wb1.z,wb1.w};
          #pragma unroll
          for (int j = 0; j < 8; j++) {
            const int h = hc + j;
            ulonglong2 u0 = *(const ulonglong2*)&H1s[h*NB + b0];
            ulonglong2 u1 = *(const ulonglong2*)&H1s[h*NB + b0 + 4];
            unsigned long long A0 = pack2(wA[j], wA[j]);
            unsigned long long A1 = pack2(wB[j], wB[j]);
            ac[0][0] = fma2(A0, u0.x, ac[0][0]);
            ac[0][1] = fma2(A0, u0.y, ac[0][1]);
            ac[0][2] = fma2(A0, u1.x, ac[0][2]);
            ac[0][3] = fma2(A0, u1.y, ac[0][3]);
            ac[1][0] = fma2(A1, u0.x, ac[1][0]);
            ac[1][1] = fma2(A1, u0.y, ac[1][1]);
            ac[1][2] = fma2(A1, u1.x, ac[1][2]);
            ac[1][3] = fma2(A1, u1.y, ac[1][3]);
          }
        }
        float part[8];
        #pragma unroll
        for (int j = 0; j < 8; j++) part[j] = 0.f;
        #pragma unroll
        for (int i = 0; i < 2; i++) {
          float bb = b2s[c0 + i];
          const float* dxr = i ? dxr1 : dxr0;
          #pragma unroll
          for (int p = 0; p < 4; p++) {
            float d0, d1; unpack2(ac[i][p], d0, d1);
            part[2*p]   += fast_tanh(d0 + bb) * dxr[2*p];
            part[2*p+1] += fast_tanh(d1 + bb) * dxr[2*p+1];
          }
        }
        #pragma unroll
        for (int j = 0; j < 8; j++) red[cp*NB + b0 + j] = part[j];
        __syncthreads();
        if (tid < NB) {
          float kv = 0.f;
          #pragma unroll
          for (int q = 0; q < 16; q++) kv += red[q*NB + tid];
          __stcg(&g_k[s][tid*NH + bid], kv);
        }
      }
      gbar();
    }
    if (exit_all) break;

    // ======== phase C : accept/reject (CTA = batch) ========
    {
      const float t = scal[0], dtv = scal[1], dt_c = scal[2];
      if (tid < NH) {
        int h = tid;
        float k1 = __ldcg(&g_k[0][bid*NH+h]);
        float k3 = __ldcg(&g_k[2][bid*NH+h]);
        float k4 = __ldcg(&g_k[3][bid*NH+h]);
        float k5 = __ldcg(&g_k[4][bid*NH+h]);
        float k6 = __ldcg(&g_k[5][bid*NH+h]);
        float k7 = __ldcg(&g_k[6][bid*NH+h]);
        float y  = g_Y[bid*NH+h];
        float yn = g_ynew[bid*NH+h];
        float ev = dt_c * (E0*k1 + E2*k3 + E3*k4 + E4*k5 + E5*k6 + E6*k7);
        float sc = ATOL_ + RTOL_ * fmaxf(fabsf(y), fabsf(yn));
        float e = ev / sc;
        float e2v = e*e;
        #pragma unroll
        for (int o = 16; o > 0; o >>= 1) e2v += __shfl_down_sync(0xffffffffu, e2v, o);
        if ((tid & 31) == 0) red[tid >> 5] = e2v;
      }
      __syncthreads();
      if (tid == 0) {
        float ssum = red[0] + red[1] + red[2] + red[3];
        float err = sqrtf(ssum * (1.f/(float)NH));
        bool accept = (err <= 1.0f);
        float fac = 0.9f * powf(fmaxf(err, 1e-9f), -0.2f);
        fac = fminf(fmaxf(fac, 0.2f), 10.f);
        bool done = (t >= tEnd - 1e-8f);
        bool adv = accept && !done;
        float t_new = adv ? (t + dt_c) : t;
        g_t[bid]  = t_new;
        g_dt[bid] = done ? dtv : (dt_c * fac);
        scal[3] = adv ? 1.f : 0.f;
        if (!counted && t_new >= tEnd - 1e-8f) {
          atomicAdd(&g_ndone, 1u);
          counted = true;
        }
      }
      __syncthreads();
      if (tid < NH && scal[3] != 0.f) g_Y[bid*NH + tid] = g_ynew[bid*NH + tid];
      __syncthreads();
    }
  }

  if (tid < NO) {
    float acc = lin_b[tid];
    #pragma unroll 4
    for (int h = 0; h < NH; h++)
      acc = fmaf(lin_w[tid*NH + h], g_Y[bid*NH + h], acc);
    out[bid*NO + tid] = acc;
  }
}

extern "C" void kernel_launch(void* const* d_in, const int* in_sizes, int n_in,
                              void* d_out, int out_size) {
  const float* ts    = (const float*)d_in[0];
  const float* xs    = (const float*)d_in[1];
  const float* W1    = (const float*)d_in[2];
  const float* b1    = (const float*)d_in[3];
  const float* W2    = (const float*)d_in[4];
  const float* b2    = (const float*)d_in[5];
  const float* lin_w = (const float*)d_in[6];
  const float* lin_b = (const float*)d_in[7];
  float* out = (float*)d_out;
  cudaFuncSetAttribute(cde_kernel, cudaFuncAttributeMaxDynamicSharedMemorySize, SMEM_BYTES);
  cde_kernel<<<NCTA, NTHR, SMEM_BYTES>>>(ts, xs, W1, b1, W2, b2, lin_w, lin_b, out);
}

// round 4
// speedup vs baseline: 27.7972x; 1.3181x over previous
#include <cuda_runtime.h>

#define NB 128
#define NT 128
#define NC 32
#define NH 128
#define NO 10
#define NCTA 128
#define NTHR 256
#define MAXSTEPS 64
#define RTOL_ 1e-3f
#define ATOL_ 1e-3f
#define DXP 129

#define OFF_W1T 0
#define OFF_H1S (OFF_W1T + NH*NH)
#define OFF_W2S (OFF_H1S + NH*NB)
#define OFF_DXT (OFF_W2S + 32*NH)
#define OFF_RED (OFF_DXT + NC*DXP)
#define OFF_TS  (OFF_RED + 16*NB)
#define OFF_B1  (OFF_TS + NT)
#define OFF_B2  (OFF_B1 + NH)
#define OFF_YS  (OFF_B2 + 32)
#define OFF_SC  (OFF_YS + NH)
#define SMEM_FLOATS (OFF_SC + 8)
#define SMEM_BYTES (SMEM_FLOATS * 4)

__device__ __align__(16) float g_Y[NB*NH];
__device__ __align__(16) float g_ynew[NB*NH];
__device__ __align__(16) float g_t[NB];
__device__ __align__(16) float g_dt[NB];
__device__ __align__(16) float g_k[7][NB*NH];
__device__ __align__(16) float g_H1[NH*NB];
__device__ __align__(16) float g_dX[NB*NC];
__device__ __align__(128) unsigned g_flags[NCTA*32];  // 128B stride per CTA
__device__ unsigned g_gen;
__device__ unsigned g_ndone;

__constant__ float A_TAB[7][6] = {
  {0.f,0.f,0.f,0.f,0.f,0.f},
  {(float)(1.0/5.0),0.f,0.f,0.f,0.f,0.f},
  {(float)(3.0/40.0),(float)(9.0/40.0),0.f,0.f,0.f,0.f},
  {(float)(44.0/45.0),(float)(-56.0/15.0),(float)(32.0/9.0),0.f,0.f,0.f},
  {(float)(19372.0/6561.0),(float)(-25360.0/2187.0),(float)(64448.0/6561.0),(float)(-212.0/729.0),0.f,0.f},
  {(float)(9017.0/3168.0),(float)(-355.0/33.0),(float)(46732.0/5247.0),(float)(49.0/176.0),(float)(-5103.0/18656.0),0.f},
  {(float)(35.0/384.0),0.f,(float)(500.0/1113.0),(float)(125.0/192.0),(float)(-2187.0/6784.0),(float)(11.0/84.0)},
};
__constant__ float C_TAB[7] = {0.f,(float)(1.0/5.0),(float)(3.0/10.0),(float)(4.0/5.0),(float)(8.0/9.0),1.f,1.f};

#define E0 ((float)(71.0/57600.0))
#define E2 ((float)(-71.0/16695.0))
#define E3 ((float)(71.0/1920.0))
#define E4 ((float)(-17253.0/339200.0))
#define E5 ((float)(22.0/525.0))
#define E6 ((float)(-1.0/40.0))

__device__ __forceinline__ unsigned long long fma2(unsigned long long a, unsigned long long b, unsigned long long c) {
  unsigned long long d;
  asm("fma.rn.f32x2 %0, %1, %2, %3;" : "=l"(d) : "l"(a), "l"(b), "l"(c));
  return d;
}
__device__ __forceinline__ unsigned long long pack2(float x, float y) {
  unsigned long long d; asm("mov.b64 %0, {%1, %2};" : "=l"(d) : "f"(x), "f"(y)); return d;
}
__device__ __forceinline__ void unpack2(unsigned long long v, float& x, float& y) {
  asm("mov.b64 {%0, %1}, %2;" : "=f"(x), "=f"(y) : "l"(v));
}
__device__ __forceinline__ unsigned ld_u32_cg(const unsigned* p) {
  unsigned v;
  asm volatile("ld.global.cg.u32 %0, [%1];" : "=r"(v) : "l"(p));
  return v;
}
__device__ __forceinline__ void st_u32_cg(unsigned* p, unsigned v) {
  asm volatile("st.global.cg.u32 [%0], %1;" :: "l"(p), "r"(v) : "memory");
}
__device__ __forceinline__ float fast_tanh(float x) {
  x = fminf(fmaxf(x, -9.f), 9.f);
  float e = __expf(2.f * x);
  return __fdividef(e - 1.f, e + 1.f);
}

// Distributed flag barrier. Monotone seq; no resets (replay-safe: every CTA
// snapshots base=g_gen before any CTA can advance it, since advancement
// requires all arrivals at barrier 1).
__device__ __forceinline__ void gbar(unsigned seq) {
  __syncthreads();
  const int tid = threadIdx.x;
  if (tid == 0) {
    __threadfence();
    st_u32_cg(&g_flags[blockIdx.x * 32], seq);
  }
  if (blockIdx.x == 0) {
    if (tid < NCTA) {
      while ((int)(ld_u32_cg(&g_flags[tid * 32]) - seq) < 0) { }
    }
    __syncthreads();
    if (tid == 0) {
      __threadfence();
      st_u32_cg(&g_gen, seq);
    }
  } else {
    if (tid == 0) {
      while ((int)(ld_u32_cg(&g_gen) - seq) < 0) { }
      __threadfence();
    }
  }
  __syncthreads();
}

__global__ __launch_bounds__(NTHR, 1)
void cde_kernel(const float* __restrict__ ts, const float* __restrict__ xs,
                const float* __restrict__ W1, const float* __restrict__ b1,
                const float* __restrict__ W2, const float* __restrict__ b2,
                const float* __restrict__ lin_w, const float* __restrict__ lin_b,
                float* __restrict__ out)
{
  extern __shared__ float sm[];
  float* W1T = sm + OFF_W1T;
  float* H1s = sm + OFF_H1S;
  float* W2s = sm + OFF_W2S;
  float* dXT = sm + OFF_DXT;
  float* red = sm + OFF_RED;
  float* tss = sm + OFF_TS;
  float* b1s = sm + OFF_B1;
  float* b2s = sm + OFF_B2;
  float* Ysm = sm + OFF_YS;
  float* scal= sm + OFF_SC;

  const int tid = threadIdx.x;
  const int bid = blockIdx.x;

  // replay-safe monotone bases (read before anyone can advance them)
  const unsigned base    = ld_u32_cg(&g_gen);
  const unsigned base_nd = ld_u32_cg(&g_ndone);
  unsigned seq = base;

  for (int i = tid; i < NH*NH; i += NTHR) { int h = i >> 7, k = i & 127; W1T[k*NH + h] = W1[i]; }
  for (int i = tid; i < 32*NH; i += NTHR) W2s[i] = W2[bid*32*NH + i];
  for (int i = tid; i < NT; i += NTHR) tss[i] = ts[i];
  for (int i = tid; i < NH; i += NTHR) b1s[i] = b1[i];
  if (tid < 32) b2s[tid] = b2[bid*32 + tid];
  if (tid < NH) g_Y[bid*NH + tid] = 0.f;
  if (tid == 0) { g_t[bid] = ts[0]; g_dt[bid] = 0.01f; }
  __syncthreads();
  const float tEnd = tss[NT-1];
  const float* xb = xs + (size_t)bid*NT*NC;

  bool counted = false;
  bool exit_all = false;

  for (int step = 0; step < MAXSTEPS && !exit_all; step++) {
    for (int s = 0; s < 7; s++) {
      // ======== phase A : CTA = batch ========
      if (tid == 0) {
        float t = g_t[bid], dtv = g_dt[bid];
        float dt_c = fminf(dtv, tEnd - t);
        scal[0] = t; scal[1] = dtv; scal[2] = dt_c;
      }
      __syncthreads();
      const float tcur = scal[0];
      const float dt_c = scal[2];
      if (tid < NH) {
        float y = g_Y[bid*NH + tid];
        float ysv;
        if (s == 0) ysv = y;
        else {
          float acc = 0.f;
          for (int j = 0; j < s; j++)
            acc += A_TAB[s][j] * __ldcg(&g_k[j][bid*NH + tid]);
          ysv = y + dt_c * acc;
        }
        Ysm[tid] = ysv;
        if (s == 6) g_ynew[bid*NH + tid] = ysv;
      } else if (tid < NH + NC) {
        int c = tid - NH;
        float tq = tcur + C_TAB[s] * dt_c;
        int lo = 0, hi = NT;
        while (lo < hi) { int mid = (lo + hi) >> 1; if (tss[mid] <= tq) lo = mid + 1; else hi = mid; }
        int idx = lo - 1; if (idx < 0) idx = 0; if (idx > NT-2) idx = NT-2;
        float t0 = tss[idx], t1 = tss[idx+1];
        float hh = t1 - t0;
        float sfr = (tq - t0) / hh;
        float dh00 = 6.f*sfr*sfr - 6.f*sfr;
        float dh10 = 3.f*sfr*sfr - 4.f*sfr + 1.f;
        float dh11 = 3.f*sfr*sfr - 2.f*sfr;
        float x0 = __ldg(&xb[idx*NC + c]);
        float x1 = __ldg(&xb[(idx+1)*NC + c]);
        float mi1 = (x1 - x0) / hh;
        float mi;
        if (idx == 0) mi = (x1 - x0) / (tss[1] - tss[0]);
        else { float xm1 = __ldg(&xb[(idx-1)*NC + c]); mi = (x0 - xm1) / (tss[idx] - tss[idx-1]); }
        float dx = (dh00*x0 - dh00*x1) / hh + dh10*mi + dh11*mi1;
        __stcg(&g_dX[bid*NC + c], dx);
      }
      __syncthreads();
      {
        int h = tid & 127;
        int half = tid >> 7;
        const int kb = half * 64;
        float a0=0.f,a1=0.f,a2=0.f,a3=0.f;
        #pragma unroll 4
        for (int k = 0; k < 64; k += 4) {
          float4 yv = *(const float4*)&Ysm[kb + k];
          a0 = fmaf(W1T[(kb+k  )*NH + h], yv.x, a0);
          a1 = fmaf(W1T[(kb+k+1)*NH + h], yv.y, a1);
          a2 = fmaf(W1T[(kb+k+2)*NH + h], yv.z, a2);
          a3 = fmaf(W1T[(kb+k+3)*NH + h], yv.w, a3);
        }
        red[half*NH + h] = (a0+a1)+(a2+a3);
      }
      __syncthreads();
      if (tid < NH) {
        float h1 = fmaxf(b1s[tid] + red[tid] + red[NH + tid], 0.f);
        __stcg(&g_H1[tid*NB + bid], h1);
      }
      gbar(++seq);

      if (s == 0) {
        if (tid == 0) scal[4] = (float)(ld_u32_cg(&g_ndone) - base_nd);
        __syncthreads();
        if (scal[4] == (float)NB) { exit_all = true; break; }
      }

      // ======== phase B : CTA = hidden unit ========
      {
        const float4* src = (const float4*)g_H1;
        for (int i = tid; i < (NH*NB)/4; i += NTHR)
          ((float4*)H1s)[i] = __ldcg(src + i);
        for (int i = tid; i < NB*NC; i += NTHR) {
          int c = i & 31, b = i >> 5;
          dXT[c*DXP + b] = __ldcg(&g_dX[b*NC + c]);
        }
        __syncthreads();

        const int cp = tid >> 4;
        const int bo = tid & 15;
        const int c0 = cp * 2;
        const int b0 = bo * 8;
        float dxr0[8], dxr1[8];
        #pragma unroll
        for (int j = 0; j < 8; j++) {
          dxr0[j] = dXT[c0*DXP + b0 + j];
          dxr1[j] = dXT[(c0+1)*DXP + b0 + j];
        }
        unsigned long long ac[2][4];
        #pragma unroll
        for (int i = 0; i < 2; i++)
          #pragma unroll
          for (int p = 0; p < 4; p++) ac[i][p] = pack2(0.f, 0.f);

        #pragma unroll 2
        for (int hc = 0; hc < NH; hc += 8) {
          float4 wa0 = *(const float4*)&W2s[c0*NH + hc];
          float4 wa1 = *(const float4*)&W2s[c0*NH + hc + 4];
          float4 wb0 = *(const float4*)&W2s[(c0+1)*NH + hc];
          float4 wb1 = *(const float4*)&W2s[(c0+1)*NH + hc + 4];
          const float wA[8] = {wa0.x,wa0.y,wa0.z,wa0.w,wa1.x,wa1.y,wa1.z,wa1.w};
          const float wB[8] = {wb0.x,wb0.y,wb0.z,wb0.w,wb1.x,wb1.y,wb1.z,wb1.w};
          #pragma unroll
          for (int j = 0; j < 8; j++) {
            const int h = hc + j;
            ulonglong2 u0 = *(const ulonglong2*)&H1s[h*NB + b0];
            ulonglong2 u1 = *(const ulonglong2*)&H1s[h*NB + b0 + 4];
            unsigned long long A0 = pack2(wA[j], wA[j]);
            unsigned long long A1 = pack2(wB[j], wB[j]);
            ac[0][0] = fma2(A0, u0.x, ac[0][0]);
            ac[0][1] = fma2(A0, u0.y, ac[0][1]);
            ac[0][2] = fma2(A0, u1.x, ac[0][2]);
            ac[0][3] = fma2(A0, u1.y, ac[0][3]);
            ac[1][0] = fma2(A1, u0.x, ac[1][0]);
            ac[1][1] = fma2(A1, u0.y, ac[1][1]);
            ac[1][2] = fma2(A1, u1.x, ac[1][2]);
            ac[1][3] = fma2(A1, u1.y, ac[1][3]);
          }
        }
        float part[8];
        #pragma unroll
        for (int j = 0; j < 8; j++) part[j] = 0.f;
        #pragma unroll
        for (int i = 0; i < 2; i++) {
          float bb = b2s[c0 + i];
          const float* dxr = i ? dxr1 : dxr0;
          #pragma unroll
          for (int p = 0; p < 4; p++) {
            float d0, d1; unpack2(ac[i][p], d0, d1);
            part[2*p]   += fast_tanh(d0 + bb) * dxr[2*p];
            part[2*p+1] += fast_tanh(d1 + bb) * dxr[2*p+1];
          }
        }
        #pragma unroll
        for (int j = 0; j < 8; j++) red[cp*NB + b0 + j] = part[j];
        __syncthreads();
        if (tid < NB) {
          float kv = 0.f;
          #pragma unroll
          for (int q = 0; q < 16; q++) kv += red[q*NB + tid];
          __stcg(&g_k[s][tid*NH + bid], kv);
        }
      }
      gbar(++seq);
    }
    if (exit_all) break;

    // ======== phase C : accept/reject (CTA = batch) ========
    {
      const float t = scal[0], dtv = scal[1], dt_c = scal[2];
      if (tid < NH) {
        int h = tid;
        float k1 = __ldcg(&g_k[0][bid*NH+h]);
        float k3 = __ldcg(&g_k[2][bid*NH+h]);
        float k4 = __ldcg(&g_k[3][bid*NH+h]);
        float k5 = __ldcg(&g_k[4][bid*NH+h]);
        float k6 = __ldcg(&g_k[5][bid*NH+h]);
        float k7 = __ldcg(&g_k[6][bid*NH+h]);
        float y  = g_Y[bid*NH+h];
        float yn = g_ynew[bid*NH+h];
        float ev = dt_c * (E0*k1 + E2*k3 + E3*k4 + E4*k5 + E5*k6 + E6*k7);
        float sc = ATOL_ + RTOL_ * fmaxf(fabsf(y), fabsf(yn));
        float e = ev / sc;
        float e2v = e*e;
        #pragma unroll
        for (int o = 16; o > 0; o >>= 1) e2v += __shfl_down_sync(0xffffffffu, e2v, o);
        if ((tid & 31) == 0) red[tid >> 5] = e2v;
      }
      __syncthreads();
      if (tid == 0) {
        float ssum = red[0] + red[1] + red[2] + red[3];
        float err = sqrtf(ssum * (1.f/(float)NH));
        bool accept = (err <= 1.0f);
        float fac = 0.9f * powf(fmaxf(err, 1e-9f), -0.2f);
        fac = fminf(fmaxf(fac, 0.2f), 10.f);
        bool done = (t >= tEnd - 1e-8f);
        bool adv = accept && !done;
        float t_new = adv ? (t + dt_c) : t;
        g_t[bid]  = t_new;
        g_dt[bid] = done ? dtv : (dt_c * fac);
        scal[3] = adv ? 1.f : 0.f;
        if (!counted && t_new >= tEnd - 1e-8f) {
          atomicAdd(&g_ndone, 1u);
          counted = true;
        }
      }
      __syncthreads();
      if (tid < NH && scal[3] != 0.f) g_Y[bid*NH + tid] = g_ynew[bid*NH + tid];
      __syncthreads();
    }
  }

  if (tid < NO) {
    float acc = lin_b[tid];
    #pragma unroll 4
    for (int h = 0; h < NH; h++)
      acc = fmaf(lin_w[tid*NH + h], g_Y[bid*NH + h], acc);
    out[bid*NO + tid] = acc;
  }
}

extern "C" void kernel_launch(void* const* d_in, const int* in_sizes, int n_in,
                              void* d_out, int out_size) {
  const float* ts    = (const float*)d_in[0];
  const float* xs    = (const float*)d_in[1];
  const float* W1    = (const float*)d_in[2];
  const float* b1    = (const float*)d_in[3];
  const float* W2    = (const float*)d_in[4];
  const float* b2    = (const float*)d_in[5];
  const float* lin_w = (const float*)d_in[6];
  const float* lin_b = (const float*)d_in[7];
  float* out = (float*)d_out;
  cudaFuncSetAttribute(cde_kernel, cudaFuncAttributeMaxDynamicSharedMemorySize, SMEM_BYTES);
  cde_kernel<<<NCTA, NTHR, SMEM_BYTES>>>(ts, xs, W1, b1, W2, b2, lin_w, lin_b, out);
}

// round 6
// speedup vs baseline: 30.4375x; 1.0950x over previous
#include <cuda_runtime.h>

#define NB 128
#define NT 128
#define NC 32
#define NH 128
#define NO 10
#define NCTA 128
#define NTHR 256
#define MAXSTEPS 64
#define RTOL_ 1e-3f
#define ATOL_ 1e-3f
#define DXP 129
#define W2P 132
#define REDP 130

#define OFF_W1T 0
#define OFF_H1S (OFF_W1T + NH*NH)          // 16384
#define OFF_W2S (OFF_H1S + NH*NB)          // 32768
#define OFF_DXT (OFF_W2S + 32*W2P)         // 36992
#define OFF_RED (OFF_DXT + NC*DXP)         // 41120
#define OFF_TS  (OFF_RED + 16*REDP)        // 43200
#define OFF_B1  (OFF_TS + NT)
#define OFF_B2  (OFF_B1 + NH)
#define OFF_YS  (OFF_B2 + 32)
#define OFF_SC  (OFF_YS + NH)
#define SMEM_FLOATS (OFF_SC + 8)
#define SMEM_BYTES (SMEM_FLOATS * 4)

__device__ __align__(16) float g_Y[NB*NH];
__device__ __align__(16) float g_ynew[NB*NH];
__device__ __align__(16) float g_t[NB];
__device__ __align__(16) float g_dt[NB];
__device__ __align__(16) float g_k[7][NB*NH];
__device__ __align__(16) float g_H1[NH*NB];
__device__ __align__(16) float g_dX[NB*NC];
__device__ __align__(128) unsigned g_flags[NCTA*32];  // 128B stride per CTA
__device__ unsigned g_ndone;

__constant__ float A_TAB[7][6] = {
  {0.f,0.f,0.f,0.f,0.f,0.f},
  {(float)(1.0/5.0),0.f,0.f,0.f,0.f,0.f},
  {(float)(3.0/40.0),(float)(9.0/40.0),0.f,0.f,0.f,0.f},
  {(float)(44.0/45.0),(float)(-56.0/15.0),(float)(32.0/9.0),0.f,0.f,0.f},
  {(float)(19372.0/6561.0),(float)(-25360.0/2187.0),(float)(64448.0/6561.0),(float)(-212.0/729.0),0.f,0.f},
  {(float)(9017.0/3168.0),(float)(-355.0/33.0),(float)(46732.0/5247.0),(float)(49.0/176.0),(float)(-5103.0/18656.0),0.f},
  {(float)(35.0/384.0),0.f,(float)(500.0/1113.0),(float)(125.0/192.0),(float)(-2187.0/6784.0),(float)(11.0/84.0)},
};
__constant__ float C_TAB[7] = {0.f,(float)(1.0/5.0),(float)(3.0/10.0),(float)(4.0/5.0),(float)(8.0/9.0),1.f,1.f};

#define E0 ((float)(71.0/57600.0))
#define E2 ((float)(-71.0/16695.0))
#define E3 ((float)(71.0/1920.0))
#define E4 ((float)(-17253.0/339200.0))
#define E5 ((float)(22.0/525.0))
#define E6 ((float)(-1.0/40.0))

__device__ __forceinline__ unsigned long long fma2(unsigned long long a, unsigned long long b, unsigned long long c) {
  unsigned long long d;
  asm("fma.rn.f32x2 %0, %1, %2, %3;" : "=l"(d) : "l"(a), "l"(b), "l"(c));
  return d;
}
__device__ __forceinline__ unsigned long long pack2(float x, float y) {
  unsigned long long d; asm("mov.b64 %0, {%1, %2};" : "=l"(d) : "f"(x), "f"(y)); return d;
}
__device__ __forceinline__ void unpack2(unsigned long long v, float& x, float& y) {
  asm("mov.b64 {%0, %1}, %2;" : "=f"(x), "=f"(y) : "l"(v));
}
__device__ __forceinline__ unsigned ld_u32_cg(const unsigned* p) {
  unsigned v;
  asm volatile("ld.global.cg.u32 %0, [%1];" : "=r"(v) : "l"(p));
  return v;
}
__device__ __forceinline__ void st_u32_cg(unsigned* p, unsigned v) {
  asm volatile("st.global.cg.u32 [%0], %1;" :: "l"(p), "r"(v) : "memory");
}
__device__ __forceinline__ float fast_tanh(float x) {
  x = fminf(fmaxf(x, -9.f), 9.f);
  float e = __expf(2.f * x);
  return __fdividef(e - 1.f, e + 1.f);
}

// All-poll distributed barrier: each CTA publishes its flag, then every CTA's
// threads 0..127 each poll one flag. Monotone seq; no resets (replay-safe:
// each CTA snapshots its flag base before anyone can advance).
__device__ __forceinline__ void gbar(unsigned seq) {
  __syncthreads();
  const int tid = threadIdx.x;
  if (tid == 0) {
    __threadfence();
    st_u32_cg(&g_flags[blockIdx.x * 32], seq);
  }
  if (tid < NCTA) {
    while ((int)(ld_u32_cg(&g_flags[tid * 32]) - seq) < 0) { }
  }
  __threadfence();
  __syncthreads();
}

__global__ __launch_bounds__(NTHR, 1)
void cde_kernel(const float* __restrict__ ts, const float* __restrict__ xs,
                const float* __restrict__ W1, const float* __restrict__ b1,
                const float* __restrict__ W2, const float* __restrict__ b2,
                const float* __restrict__ lin_w, const float* __restrict__ lin_b,
                float* __restrict__ out)
{
  extern __shared__ float sm[];
  float* W1T = sm + OFF_W1T;
  float* H1s = sm + OFF_H1S;
  float* W2s = sm + OFF_W2S;
  float* dXT = sm + OFF_DXT;
  float* red = sm + OFF_RED;
  float* tss = sm + OFF_TS;
  float* b1s = sm + OFF_B1;
  float* b2s = sm + OFF_B2;
  float* Ysm = sm + OFF_YS;
  float* scal= sm + OFF_SC;

  const int tid = threadIdx.x;
  const int bid = blockIdx.x;

  // replay-safe monotone bases (read before anyone can advance them)
  const unsigned base    = ld_u32_cg(&g_flags[bid * 32]);
  const unsigned base_nd = ld_u32_cg(&g_ndone);
  unsigned seq = base;

  for (int i = tid; i < NH*NH; i += NTHR) { int h = i >> 7, k = i & 127; W1T[k*NH + h] = W1[i]; }
  for (int i = tid; i < 32*NH; i += NTHR) { int c = i >> 7, h = i & 127; W2s[c*W2P + h] = W2[bid*32*NH + i]; }
  for (int i = tid; i < NT; i += NTHR) tss[i] = ts[i];
  for (int i = tid; i < NH; i += NTHR) b1s[i] = b1[i];
  if (tid < 32) b2s[tid] = b2[bid*32 + tid];
  if (tid < NH) g_Y[bid*NH + tid] = 0.f;
  if (tid == 0) { g_t[bid] = ts[0]; g_dt[bid] = 0.01f; }
  __syncthreads();
  const float tEnd = tss[NT-1];
  const float* xb = xs + (size_t)bid*NT*NC;

  bool counted = false;
  bool exit_all = false;

  for (int step = 0; step < MAXSTEPS && !exit_all; step++) {
    for (int s = 0; s < 7; s++) {
      // ======== phase A : CTA = batch ========
      if (tid == 0) {
        float t = g_t[bid], dtv = g_dt[bid];
        float dt_c = fminf(dtv, tEnd - t);
        scal[0] = t; scal[1] = dtv; scal[2] = dt_c;
      }
      __syncthreads();
      const float tcur = scal[0];
      const float dt_c = scal[2];
      if (tid < NH) {
        float y = g_Y[bid*NH + tid];
        float ysv;
        if (s == 0) ysv = y;
        else {
          float acc = 0.f;
          for (int j = 0; j < s; j++)
            acc += A_TAB[s][j] * __ldcg(&g_k[j][bid*NH + tid]);
          ysv = y + dt_c * acc;
        }
        Ysm[tid] = ysv;
        if (s == 6) g_ynew[bid*NH + tid] = ysv;
      } else if (tid < NH + NC) {
        int c = tid - NH;
        float tq = tcur + C_TAB[s] * dt_c;
        int lo = 0, hi = NT;
        while (lo < hi) { int mid = (lo + hi) >> 1; if (tss[mid] <= tq) lo = mid + 1; else hi = mid; }
        int idx = lo - 1; if (idx < 0) idx = 0; if (idx > NT-2) idx = NT-2;
        float t0 = tss[idx], t1 = tss[idx+1];
        float hh = t1 - t0;
        float sfr = (tq - t0) / hh;
        float dh00 = 6.f*sfr*sfr - 6.f*sfr;
        float dh10 = 3.f*sfr*sfr - 4.f*sfr + 1.f;
        float dh11 = 3.f*sfr*sfr - 2.f*sfr;
        float x0 = __ldg(&xb[idx*NC + c]);
        float x1 = __ldg(&xb[(idx+1)*NC + c]);
        float mi1 = (x1 - x0) / hh;
        float mi;
        if (idx == 0) mi = (x1 - x0) / (tss[1] - tss[0]);
        else { float xm1 = __ldg(&xb[(idx-1)*NC + c]); mi = (x0 - xm1) / (tss[idx] - tss[idx-1]); }
        float dx = (dh00*x0 - dh00*x1) / hh + dh10*mi + dh11*mi1;
        __stcg(&g_dX[bid*NC + c], dx);
      }
      __syncthreads();
      {
        int h = tid & 127;
        int half = tid >> 7;
        const int kb = half * 64;
        float a0=0.f,a1=0.f,a2=0.f,a3=0.f;
        #pragma unroll 4
        for (int k = 0; k < 64; k += 4) {
          float4 yv = *(const float4*)&Ysm[kb + k];
          a0 = fmaf(W1T[(kb+k  )*NH + h], yv.x, a0);
          a1 = fmaf(W1T[(kb+k+1)*NH + h], yv.y, a1);
          a2 = fmaf(W1T[(kb+k+2)*NH + h], yv.z, a2);
          a3 = fmaf(W1T[(kb+k+3)*NH + h], yv.w, a3);
        }
        red[half*NH + h] = (a0+a1)+(a2+a3);
      }
      __syncthreads();
      if (tid < NH) {
        float h1 = fmaxf(b1s[tid] + red[tid] + red[NH + tid], 0.f);
        __stcg(&g_H1[tid*NB + bid], h1);
      }
      gbar(++seq);

      if (s == 0) {
        if (tid == 0) scal[4] = (float)(ld_u32_cg(&g_ndone) - base_nd);
        __syncthreads();
        if (scal[4] == (float)NB) { exit_all = true; break; }
      }

      // ======== phase B : CTA = hidden unit ========
      {
        const float4* src = (const float4*)g_H1;
        for (int i = tid; i < (NH*NB)/4; i += NTHR)
          ((float4*)H1s)[i] = __ldcg(src + i);
        for (int i = tid; i < NB*NC; i += NTHR) {
          int c = i & 31, b = i >> 5;
          dXT[c*DXP + b] = __ldcg(&g_dX[b*NC + c]);
        }
        __syncthreads();

        const int cp = tid & 15;      // c-pair  (warp spans all 16 -> W2 spread)
        const int bo = tid >> 4;      // b-octet (warp spans only 2 -> H1 broadcast)
        const int c0 = cp * 2;
        const int b0 = bo * 8;
        float dxr0[8], dxr1[8];
        #pragma unroll
        for (int j = 0; j < 8; j++) {
          dxr0[j] = dXT[c0*DXP + b0 + j];
          dxr1[j] = dXT[(c0+1)*DXP + b0 + j];
        }
        unsigned long long ac[2][4];
        #pragma unroll
        for (int i = 0; i < 2; i++)
          #pragma unroll
          for (int p = 0; p < 4; p++) ac[i][p] = pack2(0.f, 0.f);

        #pragma unroll 2
        for (int hc = 0; hc < NH; hc += 8) {
          float4 wa0 = *(const float4*)&W2s[c0*W2P + hc];
          float4 wa1 = *(const float4*)&W2s[c0*W2P + hc + 4];
          float4 wb0 = *(const float4*)&W2s[(c0+1)*W2P + hc];
          float4 wb1 = *(const float4*)&W2s[(c0+1)*W2P + hc + 4];
          const float wA[8] = {wa0.x,wa0.y,wa0.z,wa0.w,wa1.x,wa1.y,wa1.z,wa1.w};
          const float wB[8] = {wb0.x,wb0.y,wb0.z,wb0.w,wb1.x,wb1.y,wb1.z,wb1.w};
          #pragma unroll
          for (int j = 0; j < 8; j++) {
            const int h = hc + j;
            ulonglong2 u0 = *(const ulonglong2*)&H1s[h*NB + b0];
            ulonglong2 u1 = *(const ulonglong2*)&H1s[h*NB + b0 + 4];
            unsigned long long A0 = pack2(wA[j], wA[j]);
            unsigned long long A1 = pack2(wB[j], wB[j]);
            ac[0][0] = fma2(A0, u0.x, ac[0][0]);
            ac[0][1] = fma2(A0, u0.y, ac[0][1]);
            ac[0][2] = fma2(A0, u1.x, ac[0][2]);
            ac[0][3] = fma2(A0, u1.y, ac[0][3]);
            ac[1][0] = fma2(A1, u0.x, ac[1][0]);
            ac[1][1] = fma2(A1, u0.y, ac[1][1]);
            ac[1][2] = fma2(A1, u1.x, ac[1][2]);
            ac[1][3] = fma2(A1, u1.y, ac[1][3]);
          }
        }
        float part[8];
        #pragma unroll
        for (int j = 0; j < 8; j++) part[j] = 0.f;
        #pragma unroll
        for (int i = 0; i < 2; i++) {
          float bb = b2s[c0 + i];
          const float* dxr = i ? dxr1 : dxr0;
          #pragma unroll
          for (int p = 0; p < 4; p++) {
            float d0, d1; unpack2(ac[i][p], d0, d1);
            part[2*p]   += fast_tanh(d0 + bb) * dxr[2*p];
            part[2*p+1] += fast_tanh(d1 + bb) * dxr[2*p+1];
          }
        }
        #pragma unroll
        for (int j = 0; j < 8; j++) red[cp*REDP + b0 + j] = part[j];
        __syncthreads();
        if (tid < NB) {
          float kv = 0.f;
          #pragma unroll
          for (int q = 0; q < 16; q++) kv += red[q*REDP + tid];
          __stcg(&g_k[s][tid*NH + bid], kv);
        }
      }
      gbar(++seq);
    }
    if (exit_all) break;

    // ======== phase C : accept/reject (CTA = batch) ========
    {
      const float t = scal[0], dtv = scal[1], dt_c = scal[2];
      if (tid < NH) {
        int h = tid;
        float k1 = __ldcg(&g_k[0][bid*NH+h]);
        float k3 = __ldcg(&g_k[2][bid*NH+h]);
        float k4 = __ldcg(&g_k[3][bid*NH+h]);
        float k5 = __ldcg(&g_k[4][bid*NH+h]);
        float k6 = __ldcg(&g_k[5][bid*NH+h]);
        float k7 = __ldcg(&g_k[6][bid*NH+h]);
        float y  = g_Y[bid*NH+h];
        float yn = g_ynew[bid*NH+h];
        float ev = dt_c * (E0*k1 + E2*k3 + E3*k4 + E4*k5 + E5*k6 + E6*k7);
        float sc = ATOL_ + RTOL_ * fmaxf(fabsf(y), fabsf(yn));
        float e = ev / sc;
        float e2v = e*e;
        #pragma unroll
        for (int o = 16; o > 0; o >>= 1) e2v += __shfl_down_sync(0xffffffffu, e2v, o);
        if ((tid & 31) == 0) red[tid >> 5] = e2v;
      }
      __syncthreads();
      if (tid == 0) {
        float ssum = red[0] + red[1] + red[2] + red[3];
        float err = sqrtf(ssum * (1.f/(float)NH));
        bool accept = (err <= 1.0f);
        float fac = 0.9f * powf(fmaxf(err, 1e-9f), -0.2f);
        fac = fminf(fmaxf(fac, 0.2f), 10.f);
        bool done = (t >= tEnd - 1e-8f);
        bool adv = accept && !done;
        float t_new = adv ? (t + dt_c) : t;
        g_t[bid]  = t_new;
        g_dt[bid] = done ? dtv : (dt_c * fac);
        scal[3] = adv ? 1.f : 0.f;
        if (!counted && t_new >= tEnd - 1e-8f) {
          atomicAdd(&g_ndone, 1u);
          counted = true;
        }
      }
      __syncthreads();
      if (tid < NH && scal[3] != 0.f) g_Y[bid*NH + tid] = g_ynew[bid*NH + tid];
      __syncthreads();
    }
  }

  if (tid < NO) {
    float acc = lin_b[tid];
    #pragma unroll 4
    for (int h = 0; h < NH; h++)
      acc = fmaf(lin_w[tid*NH + h], g_Y[bid*NH + h], acc);
    out[bid*NO + tid] = acc;
  }
}

extern "C" void kernel_launch(void* const* d_in, const int* in_sizes, int n_in,
                              void* d_out, int out_size) {
  const float* ts    = (const float*)d_in[0];
  const float* xs    = (const float*)d_in[1];
  const float* W1    = (const float*)d_in[2];
  const float* b1    = (const float*)d_in[3];
  const float* W2    = (const float*)d_in[4];
  const float* b2    = (const float*)d_in[5];
  const float* lin_w = (const float*)d_in[6];
  const float* lin_b = (const float*)d_in[7];
  float* out = (float*)d_out;
  cudaFuncSetAttribute(cde_kernel, cudaFuncAttributeMaxDynamicSharedMemorySize, SMEM_BYTES);
  cde_kernel<<<NCTA, NTHR, SMEM_BYTES>>>(ts, xs, W1, b1, W2, b2, lin_w, lin_b, out);
}

// round 8
// speedup vs baseline: 43.5243x; 1.4300x over previous
#include <cuda_runtime.h>
#include <cuda_bf16.h>
#include <cstdint>

#define NB 128
#define NT 128
#define NC 32
#define NH 128
#define NO 10
#define NCTA 128
#define NTHR 256
#define MAXSTEPS 64

// ---- smem layout (float offsets) ----
#define OFF_W1T 0          // 16384
#define OFF_W2HI 16384     // 2176 u32 (32 rows x 68)
#define OFF_W2LO 18560     // 2176
#define OFF_DXS 20736      // 4224 (128 x 33)
#define OFF_RED 24960      // 256
#define OFF_TS  25216      // 128
#define OFF_B1  25344      // 128
#define OFF_B2  25472      // 32
#define OFF_YS  25504      // 128
#define OFF_H1T 25632      // 128
#define OFF_SC  25760      // 8
#define SMEM_FLOATS 25768
#define SMEM_BYTES (SMEM_FLOATS * 4)
#define W2PR 68            // u32 row stride for W2 packs (banks 4g+q, conflict-free)
#define DXPR 33

__device__ __align__(16) float g_Y[NB*NH];
__device__ __align__(16) float g_ynew[NB*NH];
__device__ __align__(16) float g_t[NB];
__device__ __align__(16) float g_dt[NB];
__device__ __align__(16) float g_k[7][NB*NH];
__device__ __align__(16) unsigned g_H1hi[NB*64];
__device__ __align__(16) unsigned g_H1lo[NB*64];
__device__ __align__(16) float g_dX[NB*NC];
__device__ __align__(128) unsigned g_flags[NCTA*32];
__device__ unsigned g_ndone;

__constant__ float A_TAB[7][6] = {
  {0.f,0.f,0.f,0.f,0.f,0.f},
  {(float)(1.0/5.0),0.f,0.f,0.f,0.f,0.f},
  {(float)(3.0/40.0),(float)(9.0/40.0),0.f,0.f,0.f,0.f},
  {(float)(44.0/45.0),(float)(-56.0/15.0),(float)(32.0/9.0),0.f,0.f,0.f},
  {(float)(19372.0/6561.0),(float)(-25360.0/2187.0),(float)(64448.0/6561.0),(float)(-212.0/729.0),0.f,0.f},
  {(float)(9017.0/3168.0),(float)(-355.0/33.0),(float)(46732.0/5247.0),(float)(49.0/176.0),(float)(-5103.0/18656.0),0.f},
  {(float)(35.0/384.0),0.f,(float)(500.0/1113.0),(float)(125.0/192.0),(float)(-2187.0/6784.0),(float)(11.0/84.0)},
};
__constant__ float C_TAB[7] = {0.f,(float)(1.0/5.0),(float)(3.0/10.0),(float)(4.0/5.0),(float)(8.0/9.0),1.f,1.f};

#define E0 ((float)(71.0/57600.0))
#define E2 ((float)(-71.0/16695.0))
#define E3 ((float)(71.0/1920.0))
#define E4 ((float)(-17253.0/339200.0))
#define E5 ((float)(22.0/525.0))
#define E6 ((float)(-1.0/40.0))

__device__ __forceinline__ unsigned ld_u32_cg(const unsigned* p) {
  unsigned v; asm volatile("ld.global.cg.u32 %0, [%1];" : "=r"(v) : "l"(p)); return v;
}
__device__ __forceinline__ void st_u32_cg(unsigned* p, unsigned v) {
  asm volatile("st.global.cg.u32 [%0], %1;" :: "l"(p), "r"(v) : "memory");
}
__device__ __forceinline__ float fast_tanh(float x) {
  x = fminf(fmaxf(x, -9.f), 9.f);
  float e = __expf(2.f * x);
  return __fdividef(e - 1.f, e + 1.f);
}
// pack (elem0, elem1): elem0 -> low 16 bits
__device__ __forceinline__ uint32_t pack_bf16x2(float e0, float e1) {
  uint32_t d;
  asm("cvt.rn.bf16x2.f32 %0, %1, %2;" : "=r"(d) : "f"(e1), "f"(e0));
  return d;
}
__device__ __forceinline__ void mma_bf16(float* d, uint32_t a0, uint32_t a1, uint32_t a2, uint32_t a3,
                                         uint32_t b0, uint32_t b1) {
  asm volatile(
    "mma.sync.aligned.m16n8k16.row.col.f32.bf16.bf16.f32 "
    "{%0,%1,%2,%3}, {%4,%5,%6,%7}, {%8,%9}, {%0,%1,%2,%3};"
    : "+f"(d[0]), "+f"(d[1]), "+f"(d[2]), "+f"(d[3])
    : "r"(a0), "r"(a1), "r"(a2), "r"(a3), "r"(b0), "r"(b1));
}

// all-poll distributed barrier (monotone seq, replay-safe)
__device__ __forceinline__ void gbar(unsigned seq) {
  __syncthreads();
  const int tid = threadIdx.x;
  if (tid == 0) {
    __threadfence();
    st_u32_cg(&g_flags[blockIdx.x * 32], seq);
  }
  if (tid < NCTA) {
    while ((int)(ld_u32_cg(&g_flags[tid * 32]) - seq) < 0) { }
  }
  __threadfence();
  __syncthreads();
}

__global__ __launch_bounds__(NTHR, 1)
void cde_kernel(const float* __restrict__ ts, const float* __restrict__ xs,
                const float* __restrict__ W1, const float* __restrict__ b1,
                const float* __restrict__ W2, const float* __restrict__ b2,
                const float* __restrict__ lin_w, const float* __restrict__ lin_b,
                float* __restrict__ out)
{
  extern __shared__ float sm[];
  float*    W1T  = sm + OFF_W1T;
  unsigned* W2hiS= (unsigned*)(sm + OFF_W2HI);
  unsigned* W2loS= (unsigned*)(sm + OFF_W2LO);
  float*    dXs  = sm + OFF_DXS;
  float*    red  = sm + OFF_RED;
  float*    tss  = sm + OFF_TS;
  float*    b1s  = sm + OFF_B1;
  float*    b2s  = sm + OFF_B2;
  float*    Ysm  = sm + OFF_YS;
  float*    H1t  = sm + OFF_H1T;
  float*    scal = sm + OFF_SC;

  const int tid = threadIdx.x;
  const int bid = blockIdx.x;
  const int wid = tid >> 5;
  const int lane = tid & 31;
  const int g = lane >> 2;     // fragment group (row within tile / B col)
  const int q = lane & 3;      // thread-in-group (k pair / D col pair)

  // replay-safe monotone bases
  const unsigned base_nd = ld_u32_cg(&g_ndone);
  unsigned seq = ld_u32_cg(&g_flags[bid * 32]);

  // ---- one-time setup ----
  for (int i = tid; i < NH*NH; i += NTHR) { int h = i >> 7, k = i & 127; W1T[k*NH + h] = W1[i]; }
  for (int i = tid; i < 32*64; i += NTHR) {
    int c = i >> 6, kq = i & 63;
    float w0 = W2[bid*32*NH + c*NH + kq*2];
    float w1 = W2[bid*32*NH + c*NH + kq*2 + 1];
    __nv_bfloat16 h0 = __float2bfloat16(w0), h1 = __float2bfloat16(w1);
    W2hiS[c*W2PR + kq] = pack_bf16x2(w0, w1);
    W2loS[c*W2PR + kq] = pack_bf16x2(w0 - __bfloat162float(h0), w1 - __bfloat162float(h1));
  }
  for (int i = tid; i < NT; i += NTHR) tss[i] = ts[i];
  for (int i = tid; i < NH; i += NTHR) b1s[i] = b1[i];
  if (tid < 32) b2s[tid] = b2[bid*32 + tid];
  if (tid < NH) g_Y[bid*NH + tid] = 0.f;
  if (tid == 0) { g_t[bid] = ts[0]; g_dt[bid] = 0.01f; }
  __syncthreads();
  const float tEnd = tss[NT-1];
  const float* xb = xs + (size_t)bid*NT*NC;

  bool counted = false;
  bool exit_all = false;

  for (int step = 0; step < MAXSTEPS && !exit_all; step++) {
    const int sb = (step == 0) ? 0 : 1;   // FSAL: k1 reused after first step
    for (int s = sb; s < 7; s++) {
      // ======== phase A : CTA = batch ========
      if (tid == 0) {
        float t = g_t[bid], dtv = g_dt[bid];
        float dt_c = fminf(dtv, tEnd - t);
        scal[0] = t; scal[1] = dtv; scal[2] = dt_c;
      }
      __syncthreads();
      const float tcur = scal[0];
      const float dt_c = scal[2];
      if (tid < NH) {
        float y = g_Y[bid*NH + tid];
        float ysv;
        if (s == 0) ysv = y;
        else {
          float acc = 0.f;
          for (int j = 0; j < s; j++)
            acc += A_TAB[s][j] * __ldcg(&g_k[j][bid*NH + tid]);
          ysv = y + dt_c * acc;
        }
        Ysm[tid] = ysv;
        if (s == 6) g_ynew[bid*NH + tid] = ysv;
      } else if (tid < NH + NC) {
        int c = tid - NH;
        float tq = tcur + C_TAB[s] * dt_c;
        int lo = 0, hi = NT;
        while (lo < hi) { int mid = (lo + hi) >> 1; if (tss[mid] <= tq) lo = mid + 1; else hi = mid; }
        int idx = lo - 1; if (idx < 0) idx = 0; if (idx > NT-2) idx = NT-2;
        float t0 = tss[idx], t1 = tss[idx+1];
        float hh = t1 - t0;
        float sfr = (tq - t0) / hh;
        float dh00 = 6.f*sfr*sfr - 6.f*sfr;
        float dh10 = 3.f*sfr*sfr - 4.f*sfr + 1.f;
        float dh11 = 3.f*sfr*sfr - 2.f*sfr;
        float x0 = __ldg(&xb[idx*NC + c]);
        float x1 = __ldg(&xb[(idx+1)*NC + c]);
        float mi1 = (x1 - x0) / hh;
        float mi;
        if (idx == 0) mi = (x1 - x0) / (tss[1] - tss[0]);
        else { float xm1 = __ldg(&xb[(idx-1)*NC + c]); mi = (x0 - xm1) / (tss[idx] - tss[idx-1]); }
        float dx = (dh00*x0 - dh00*x1) / hh + dh10*mi + dh11*mi1;
        __stcg(&g_dX[bid*NC + c], dx);
      }
      __syncthreads();
      {
        int h = tid & 127;
        int half = tid >> 7;
        const int kb = half * 64;
        float a0=0.f,a1=0.f,a2=0.f,a3=0.f;
        #pragma unroll 4
        for (int k = 0; k < 64; k += 4) {
          float4 yv = *(const float4*)&Ysm[kb + k];
          a0 = fmaf(W1T[(kb+k  )*NH + h], yv.x, a0);
          a1 = fmaf(W1T[(kb+k+1)*NH + h], yv.y, a1);
          a2 = fmaf(W1T[(kb+k+2)*NH + h], yv.z, a2);
          a3 = fmaf(W1T[(kb+k+3)*NH + h], yv.w, a3);
        }
        red[half*NH + h] = (a0+a1)+(a2+a3);
      }
      __syncthreads();
      if (tid < NH) H1t[tid] = fmaxf(b1s[tid] + red[tid] + red[NH + tid], 0.f);
      __syncthreads();
      if (tid < 64) {
        float f0 = H1t[2*tid], f1 = H1t[2*tid+1];
        uint32_t hi = pack_bf16x2(f0, f1);
        __nv_bfloat162 hb = *reinterpret_cast<__nv_bfloat162*>(&hi);
        uint32_t lo = pack_bf16x2(f0 - __bfloat162float(hb.x), f1 - __bfloat162float(hb.y));
        st_u32_cg(&g_H1hi[bid*64 + tid], hi);
        st_u32_cg(&g_H1lo[bid*64 + tid], lo);
      }
      gbar(++seq);

      if (s == sb) {
        if (tid == 0) scal[4] = (float)(ld_u32_cg(&g_ndone) - base_nd);
        __syncthreads();
        if (scal[4] == (float)NB) { exit_all = true; break; }
      }

      // ======== phase B : CTA = h-group, warp-level bf16 HMMA ========
      {
        // stage dX (all batches) into padded SMEM
        for (int i = tid; i < NB*NC; i += NTHR) {
          int b = i >> 5, c = i & 31;
          dXs[b*DXPR + c] = __ldcg(&g_dX[i]);
        }
        __syncthreads();

        const int mb = wid * 16;
        float d[4][4];
        #pragma unroll
        for (int nt = 0; nt < 4; nt++)
          #pragma unroll
          for (int r = 0; r < 4; r++) d[nt][r] = 0.f;

        const int r0off = (mb + g) * 64;
        const int r1off = (mb + g + 8) * 64;
        #pragma unroll
        for (int kk = 0; kk < 8; kk++) {
          const int kq = kk*8 + q;
          uint32_t ah0 = ld_u32_cg(&g_H1hi[r0off + kq]);
          uint32_t ah1 = ld_u32_cg(&g_H1hi[r1off + kq]);
          uint32_t ah2 = ld_u32_cg(&g_H1hi[r0off + kq + 4]);
          uint32_t ah3 = ld_u32_cg(&g_H1hi[r1off + kq + 4]);
          uint32_t al0 = ld_u32_cg(&g_H1lo[r0off + kq]);
          uint32_t al1 = ld_u32_cg(&g_H1lo[r1off + kq]);
          uint32_t al2 = ld_u32_cg(&g_H1lo[r0off + kq + 4]);
          uint32_t al3 = ld_u32_cg(&g_H1lo[r1off + kq + 4]);
          #pragma unroll
          for (int nt = 0; nt < 4; nt++) {
            const int c = nt*8 + g;
            uint32_t bh0 = W2hiS[c*W2PR + kq];
            uint32_t bh1 = W2hiS[c*W2PR + kq + 4];
            uint32_t bl0 = W2loS[c*W2PR + kq];
            uint32_t bl1 = W2loS[c*W2PR + kq + 4];
            mma_bf16(d[nt], ah0, ah1, ah2, ah3, bh0, bh1);
            mma_bf16(d[nt], al0, al1, al2, al3, bh0, bh1);
            mma_bf16(d[nt], ah0, ah1, ah2, ah3, bl0, bl1);
          }
        }

        // epilogue: tanh + dX contraction + quad reduction over c
        float part0 = 0.f, part1 = 0.f;
        const int row0 = mb + g, row1 = mb + g + 8;
        #pragma unroll
        for (int nt = 0; nt < 4; nt++) {
          const int cb = nt*8 + q*2;
          float bb0 = b2s[cb], bb1 = b2s[cb+1];
          part0 += fast_tanh(d[nt][0] + bb0) * dXs[row0*DXPR + cb]
                 + fast_tanh(d[nt][1] + bb1) * dXs[row0*DXPR + cb + 1];
          part1 += fast_tanh(d[nt][2] + bb0) * dXs[row1*DXPR + cb]
                 + fast_tanh(d[nt][3] + bb1) * dXs[row1*DXPR + cb + 1];
        }
        part0 += __shfl_xor_sync(0xffffffffu, part0, 1);
        part0 += __shfl_xor_sync(0xffffffffu, part0, 2);
        part1 += __shfl_xor_sync(0xffffffffu, part1, 1);
        part1 += __shfl_xor_sync(0xffffffffu, part1, 2);
        if (q == 0) {
          __stcg(&g_k[s][row0*NH + bid], part0);
          __stcg(&g_k[s][row1*NH + bid], part1);
        }
      }
      gbar(++seq);
    }
    if (exit_all) break;

    // ======== phase C : accept/reject + FSAL copy (CTA = batch) ========
    {
      const float t = scal[0], dtv = scal[1], dt_c = scal[2];
      float k7v = 0.f;
      if (tid < NH) {
        int h = tid;
        float k1 = __ldcg(&g_k[0][bid*NH+h]);
        float k3 = __ldcg(&g_k[2][bid*NH+h]);
        float k4 = __ldcg(&g_k[3][bid*NH+h]);
        float k5 = __ldcg(&g_k[4][bid*NH+h]);
        float k6 = __ldcg(&g_k[5][bid*NH+h]);
        float k7 = __ldcg(&g_k[6][bid*NH+h]);
        k7v = k7;
        float y  = g_Y[bid*NH+h];
        float yn = g_ynew[bid*NH+h];
        float ev = dt_c * (E0*k1 + E2*k3 + E3*k4 + E4*k5 + E5*k6 + E6*k7);
        float sc = 1e-3f + 1e-3f * fmaxf(fabsf(y), fabsf(yn));
        float e = ev / sc;
        float e2v = e*e;
        #pragma unroll
        for (int o = 16; o > 0; o >>= 1) e2v += __shfl_down_sync(0xffffffffu, e2v, o);
        if ((tid & 31) == 0) red[tid >> 5] = e2v;
      }
      __syncthreads();
      if (tid == 0) {
        float ssum = red[0] + red[1] + red[2] + red[3];
        float err = sqrtf(ssum * (1.f/(float)NH));
        bool accept = (err <= 1.0f);
        float fac = 0.9f * powf(fmaxf(err, 1e-9f), -0.2f);
        fac = fminf(fmaxf(fac, 0.2f), 10.f);
        bool done = (t >= tEnd - 1e-8f);
        bool adv = accept && !done;
        float t_new = adv ? (t + dt_c) : t;
        g_t[bid]  = t_new;
        g_dt[bid] = done ? dtv : (dt_c * fac);
        scal[3] = adv ? 1.f : 0.f;
        if (!counted && t_new >= tEnd - 1e-8f) {
          atomicAdd(&g_ndone, 1u);
          counted = true;
        }
      }
      __syncthreads();
      if (tid < NH && scal[3] != 0.f) {
        g_Y[bid*NH + tid] = g_ynew[bid*NH + tid];
        __stcg(&g_k[0][bid*NH + tid], k7v);   // FSAL: k1 <- k7 on accept
      }
      __syncthreads();
    }
  }

  if (tid < NO) {
    float acc = lin_b[tid];
    #pragma unroll 4
    for (int h = 0; h < NH; h++)
      acc = fmaf(lin_w[tid*NH + h], g_Y[bid*NH + h], acc);
    out[bid*NO + tid] = acc;
  }
}

extern "C" void kernel_launch(void* const* d_in, const int* in_sizes, int n_in,
                              void* d_out, int out_size) {
  const float* ts    = (const float*)d_in[0];
  const float* xs    = (const float*)d_in[1];
  const float* W1    = (const float*)d_in[2];
  const float* b1    = (const float*)d_in[3];
  const float* W2    = (const float*)d_in[4];
  const float* b2    = (const float*)d_in[5];
  const float* lin_w = (const float*)d_in[6];
  const float* lin_b = (const float*)d_in[7];
  float* out = (float*)d_out;
  cudaFuncSetAttribute(cde_kernel, cudaFuncAttributeMaxDynamicSharedMemorySize, SMEM_BYTES);
  cde_kernel<<<NCTA, NTHR, SMEM_BYTES>>>(ts, xs, W1, b1, W2, b2, lin_w, lin_b, out);
}

// round 9
// speedup vs baseline: 50.9106x; 1.1697x over previous
#include <cuda_runtime.h>
#include <cuda_bf16.h>
#include <cstdint>

#define NB 128
#define NT 128
#define NC 32
#define NH 128
#define NO 10
#define NCTA 128
#define NTHR 256
#define MAXSTEPS 64

// ---- smem layout (float offsets) ----
#define OFF_W1T 0          // 16384
#define OFF_W2HI 16384     // 2176 u32
#define OFF_W2LO 18560     // 2176 u32
#define OFF_H1HI 20736     // 8704 u32 (128 rows x 68)
#define OFF_H1LO 29440     // 8704 u32
#define OFF_DXS 38144      // 4224 (128 x 33)
#define OFF_RED 42368      // 256
#define OFF_TS  42624      // 128
#define OFF_B1  42752      // 128
#define OFF_B2  42880      // 32
#define OFF_YS  42912      // 128
#define OFF_SC  43040      // 8
#define SMEM_FLOATS 43048
#define SMEM_BYTES (SMEM_FLOATS * 4)   // 172192 B
#define W2PR 68
#define H1PR 68
#define DXPR 33

__device__ __align__(16) float g_Y[NB*NH];
__device__ __align__(16) float g_ynew[NB*NH];
__device__ __align__(16) float g_t[NB];
__device__ __align__(16) float g_dt[NB];
__device__ __align__(16) float g_k[7][NB*NH];
__device__ __align__(16) unsigned g_H1hi[NB*64];
__device__ __align__(16) unsigned g_H1lo[NB*64];
__device__ __align__(16) float g_dX[NB*NC];
__device__ __align__(128) unsigned g_flags[NCTA*32];
__device__ unsigned g_ndone;

__constant__ float A_TAB[7][6] = {
  {0.f,0.f,0.f,0.f,0.f,0.f},
  {(float)(1.0/5.0),0.f,0.f,0.f,0.f,0.f},
  {(float)(3.0/40.0),(float)(9.0/40.0),0.f,0.f,0.f,0.f},
  {(float)(44.0/45.0),(float)(-56.0/15.0),(float)(32.0/9.0),0.f,0.f,0.f},
  {(float)(19372.0/6561.0),(float)(-25360.0/2187.0),(float)(64448.0/6561.0),(float)(-212.0/729.0),0.f,0.f},
  {(float)(9017.0/3168.0),(float)(-355.0/33.0),(float)(46732.0/5247.0),(float)(49.0/176.0),(float)(-5103.0/18656.0),0.f},
  {(float)(35.0/384.0),0.f,(float)(500.0/1113.0),(float)(125.0/192.0),(float)(-2187.0/6784.0),(float)(11.0/84.0)},
};
__constant__ float C_TAB[7] = {0.f,(float)(1.0/5.0),(float)(3.0/10.0),(float)(4.0/5.0),(float)(8.0/9.0),1.f,1.f};

#define E0 ((float)(71.0/57600.0))
#define E2 ((float)(-71.0/16695.0))
#define E3 ((float)(71.0/1920.0))
#define E4 ((float)(-17253.0/339200.0))
#define E5 ((float)(22.0/525.0))
#define E6 ((float)(-1.0/40.0))

__device__ __forceinline__ unsigned ld_u32_cg(const unsigned* p) {
  unsigned v; asm volatile("ld.global.cg.u32 %0, [%1];" : "=r"(v) : "l"(p)); return v;
}
__device__ __forceinline__ void st_u32_cg(unsigned* p, unsigned v) {
  asm volatile("st.global.cg.u32 [%0], %1;" :: "l"(p), "r"(v) : "memory");
}
__device__ __forceinline__ float fast_tanh(float x) {
  x = fminf(fmaxf(x, -9.f), 9.f);
  float e = __expf(2.f * x);
  return __fdividef(e - 1.f, e + 1.f);
}
__device__ __forceinline__ uint32_t pack_bf16x2(float e0, float e1) {
  uint32_t d;
  asm("cvt.rn.bf16x2.f32 %0, %1, %2;" : "=r"(d) : "f"(e1), "f"(e0));
  return d;
}
__device__ __forceinline__ uint32_t smem_u32(const void* p) {
  uint32_t a;
  asm("{ .reg .u64 t; cvta.to.shared.u64 t, %1; cvt.u32.u64 %0, t; }" : "=r"(a) : "l"(p));
  return a;
}
__device__ __forceinline__ void mma_bf16(float* d, uint32_t a0, uint32_t a1, uint32_t a2, uint32_t a3,
                                         uint32_t b0, uint32_t b1) {
  asm volatile(
    "mma.sync.aligned.m16n8k16.row.col.f32.bf16.bf16.f32 "
    "{%0,%1,%2,%3}, {%4,%5,%6,%7}, {%8,%9}, {%0,%1,%2,%3};"
    : "+f"(d[0]), "+f"(d[1]), "+f"(d[2]), "+f"(d[3])
    : "r"(a0), "r"(a1), "r"(a2), "r"(a3), "r"(b0), "r"(b1));
}
__device__ __forceinline__ void ldmx4(uint32_t* r, uint32_t addr) {
  asm volatile("ldmatrix.sync.aligned.m8n8.x4.shared.b16 {%0,%1,%2,%3}, [%4];"
    : "=r"(r[0]), "=r"(r[1]), "=r"(r[2]), "=r"(r[3]) : "r"(addr));
}

// all-poll distributed barrier (monotone seq, replay-safe)
__device__ __forceinline__ void gbar(unsigned seq) {
  __syncthreads();
  const int tid = threadIdx.x;
  if (tid == 0) {
    __threadfence();
    st_u32_cg(&g_flags[blockIdx.x * 32], seq);
  }
  if (tid < NCTA) {
    while ((int)(ld_u32_cg(&g_flags[tid * 32]) - seq) < 0) { }
  }
  __threadfence();
  __syncthreads();
}

__global__ __launch_bounds__(NTHR, 1)
void cde_kernel(const float* __restrict__ ts, const float* __restrict__ xs,
                const float* __restrict__ W1, const float* __restrict__ b1,
                const float* __restrict__ W2, const float* __restrict__ b2,
                const float* __restrict__ lin_w, const float* __restrict__ lin_b,
                float* __restrict__ out)
{
  extern __shared__ float sm[];
  float*    W1T  = sm + OFF_W1T;
  unsigned* W2hiS= (unsigned*)(sm + OFF_W2HI);
  unsigned* W2loS= (unsigned*)(sm + OFF_W2LO);
  unsigned* H1hiS= (unsigned*)(sm + OFF_H1HI);
  unsigned* H1loS= (unsigned*)(sm + OFF_H1LO);
  float*    dXs  = sm + OFF_DXS;
  float*    red  = sm + OFF_RED;
  float*    tss  = sm + OFF_TS;
  float*    b1s  = sm + OFF_B1;
  float*    b2s  = sm + OFF_B2;
  float*    Ysm  = sm + OFF_YS;
  float*    scal = sm + OFF_SC;

  const int tid = threadIdx.x;
  const int bid = blockIdx.x;
  const int wid = tid >> 5;
  const int lane = tid & 31;
  const int g = lane >> 2;
  const int q = lane & 3;
  const uint32_t smb = smem_u32(sm);

  const unsigned base_nd = ld_u32_cg(&g_ndone);
  unsigned seq = ld_u32_cg(&g_flags[bid * 32]);

  // ---- one-time setup ----
  for (int i = tid; i < NH*NH; i += NTHR) { int h = i >> 7, k = i & 127; W1T[k*NH + h] = W1[i]; }
  for (int i = tid; i < 32*64; i += NTHR) {
    int c = i >> 6, kq = i & 63;
    float w0 = W2[bid*32*NH + c*NH + kq*2];
    float w1 = W2[bid*32*NH + c*NH + kq*2 + 1];
    __nv_bfloat16 h0 = __float2bfloat16(w0), h1 = __float2bfloat16(w1);
    W2hiS[c*W2PR + kq] = pack_bf16x2(w0, w1);
    W2loS[c*W2PR + kq] = pack_bf16x2(w0 - __bfloat162float(h0), w1 - __bfloat162float(h1));
  }
  for (int i = tid; i < NT; i += NTHR) tss[i] = ts[i];
  for (int i = tid; i < NH; i += NTHR) b1s[i] = b1[i];
  if (tid < 32) b2s[tid] = b2[bid*32 + tid];
  if (tid < NH) g_Y[bid*NH + tid] = 0.f;
  if (tid == 0) { g_t[bid] = ts[0]; g_dt[bid] = 0.01f; }
  __syncthreads();
  const float tEnd = tss[NT-1];
  const float* xb = xs + (size_t)bid*NT*NC;

  // ldmatrix per-lane bases (row = mb + (lane&7) + ((lane>>3)&1)*8, coltile = ((lane>>4)&1)*4)
  const int lrow = wid*16 + (lane & 7) + ((lane >> 3) & 1) * 8;
  const int lcol = ((lane >> 4) & 1) * 4;
  const uint32_t hibase = smb + (uint32_t)(OFF_H1HI + lrow*H1PR + lcol) * 4u;
  const uint32_t lobase = smb + (uint32_t)(OFF_H1LO + lrow*H1PR + lcol) * 4u;

  bool counted = false;
  bool exit_all = false;

  for (int step = 0; step < MAXSTEPS && !exit_all; step++) {
    const int sb = (step == 0) ? 0 : 1;   // FSAL
    for (int s = sb; s < 7; s++) {
      // ======== phase A : CTA = batch ========
      if (tid == 0) {
        float t = g_t[bid], dtv = g_dt[bid];
        float dt_c = fminf(dtv, tEnd - t);
        scal[0] = t; scal[1] = dtv; scal[2] = dt_c;
      }
      __syncthreads();
      const float tcur = scal[0];
      const float dt_c = scal[2];
      if (tid < NH) {
        float y = g_Y[bid*NH + tid];
        float ysv;
        if (s == 0) ysv = y;
        else {
          float acc = 0.f;
          for (int j = 0; j < s; j++)
            acc += A_TAB[s][j] * __ldcg(&g_k[j][bid*NH + tid]);
          ysv = y + dt_c * acc;
        }
        Ysm[tid] = ysv;
        if (s == 6) g_ynew[bid*NH + tid] = ysv;
      } else if (tid < NH + NC) {
        int c = tid - NH;
        float tq = tcur + C_TAB[s] * dt_c;
        int lo = 0, hi = NT;
        while (lo < hi) { int mid = (lo + hi) >> 1; if (tss[mid] <= tq) lo = mid + 1; else hi = mid; }
        int idx = lo - 1; if (idx < 0) idx = 0; if (idx > NT-2) idx = NT-2;
        float t0 = tss[idx], t1 = tss[idx+1];
        float hh = t1 - t0;
        float sfr = (tq - t0) / hh;
        float dh00 = 6.f*sfr*sfr - 6.f*sfr;
        float dh10 = 3.f*sfr*sfr - 4.f*sfr + 1.f;
        float dh11 = 3.f*sfr*sfr - 2.f*sfr;
        float x0 = __ldg(&xb[idx*NC + c]);
        float x1 = __ldg(&xb[(idx+1)*NC + c]);
        float mi1 = (x1 - x0) / hh;
        float mi;
        if (idx == 0) mi = (x1 - x0) / (tss[1] - tss[0]);
        else { float xm1 = __ldg(&xb[(idx-1)*NC + c]); mi = (x0 - xm1) / (tss[idx] - tss[idx-1]); }
        float dx = (dh00*x0 - dh00*x1) / hh + dh10*mi + dh11*mi1;
        __stcg(&g_dX[bid*NC + c], dx);
      }
      __syncthreads();
      {
        int h = tid & 127;
        int half = tid >> 7;
        const int kb = half * 64;
        float a0=0.f,a1=0.f,a2=0.f,a3=0.f;
        #pragma unroll 4
        for (int k = 0; k < 64; k += 4) {
          float4 yv = *(const float4*)&Ysm[kb + k];
          a0 = fmaf(W1T[(kb+k  )*NH + h], yv.x, a0);
          a1 = fmaf(W1T[(kb+k+1)*NH + h], yv.y, a1);
          a2 = fmaf(W1T[(kb+k+2)*NH + h], yv.z, a2);
          a3 = fmaf(W1T[(kb+k+3)*NH + h], yv.w, a3);
        }
        red[half*NH + h] = (a0+a1)+(a2+a3);
      }
      __syncthreads();
      if (tid < 64) {
        float f0 = fmaxf(b1s[2*tid]   + red[2*tid]   + red[NH + 2*tid],   0.f);
        float f1 = fmaxf(b1s[2*tid+1] + red[2*tid+1] + red[NH + 2*tid+1], 0.f);
        uint32_t hi = pack_bf16x2(f0, f1);
        __nv_bfloat162 hb = *reinterpret_cast<__nv_bfloat162*>(&hi);
        uint32_t lo = pack_bf16x2(f0 - __bfloat162float(hb.x), f1 - __bfloat162float(hb.y));
        st_u32_cg(&g_H1hi[bid*64 + tid], hi);
        st_u32_cg(&g_H1lo[bid*64 + tid], lo);
      }
      gbar(++seq);

      if (s == sb) {
        if (tid == 0) scal[4] = (float)(ld_u32_cg(&g_ndone) - base_nd);
        __syncthreads();
        if (scal[4] == (float)NB) { exit_all = true; break; }
      }

      // ======== phase B : CTA = h-group, ldmatrix + bf16 HMMA ========
      {
        // stage H1 hi/lo and dX into SMEM (coalesced)
        for (int i = tid; i < 128*16; i += NTHR) {
          int row = i >> 4, c4 = (i & 15) * 4;
          uint4 u = __ldcg((const uint4*)&g_H1hi[row*64 + c4]);
          *(uint4*)&H1hiS[row*H1PR + c4] = u;
          uint4 v = __ldcg((const uint4*)&g_H1lo[row*64 + c4]);
          *(uint4*)&H1loS[row*H1PR + c4] = v;
        }
        for (int i = tid; i < NB*NC; i += NTHR) {
          int b = i >> 5, c = i & 31;
          dXs[b*DXPR + c] = __ldcg(&g_dX[i]);
        }
        __syncthreads();

        const int mb = wid * 16;
        float d[4][4];
        #pragma unroll
        for (int nt = 0; nt < 4; nt++)
          #pragma unroll
          for (int r = 0; r < 4; r++) d[nt][r] = 0.f;

        #pragma unroll
        for (int kk = 0; kk < 8; kk++) {
          const int kq = kk*8 + q;
          uint32_t ah[4], al[4];
          ldmx4(ah, hibase + (uint32_t)kk * 32u);
          ldmx4(al, lobase + (uint32_t)kk * 32u);
          #pragma unroll
          for (int nt = 0; nt < 4; nt++) {
            const int c = nt*8 + g;
            uint32_t bh0 = W2hiS[c*W2PR + kq];
            uint32_t bh1 = W2hiS[c*W2PR + kq + 4];
            uint32_t bl0 = W2loS[c*W2PR + kq];
            uint32_t bl1 = W2loS[c*W2PR + kq + 4];
            mma_bf16(d[nt], ah[0], ah[1], ah[2], ah[3], bh0, bh1);
            mma_bf16(d[nt], al[0], al[1], al[2], al[3], bh0, bh1);
            mma_bf16(d[nt], ah[0], ah[1], ah[2], ah[3], bl0, bl1);
          }
        }

        // epilogue: tanh + dX contraction + quad reduction over c
        float part0 = 0.f, part1 = 0.f;
        const int row0 = mb + g, row1 = mb + g + 8;
        #pragma unroll
        for (int nt = 0; nt < 4; nt++) {
          const int cb = nt*8 + q*2;
          float bb0 = b2s[cb], bb1 = b2s[cb+1];
          part0 += fast_tanh(d[nt][0] + bb0) * dXs[row0*DXPR + cb]
                 + fast_tanh(d[nt][1] + bb1) * dXs[row0*DXPR + cb + 1];
          part1 += fast_tanh(d[nt][2] + bb0) * dXs[row1*DXPR + cb]
                 + fast_tanh(d[nt][3] + bb1) * dXs[row1*DXPR + cb + 1];
        }
        part0 += __shfl_xor_sync(0xffffffffu, part0, 1);
        part0 += __shfl_xor_sync(0xffffffffu, part0, 2);
        part1 += __shfl_xor_sync(0xffffffffu, part1, 1);
        part1 += __shfl_xor_sync(0xffffffffu, part1, 2);
        if (q == 0) {
          __stcg(&g_k[s][row0*NH + bid], part0);
          __stcg(&g_k[s][row1*NH + bid], part1);
        }
      }
      gbar(++seq);
    }
    if (exit_all) break;

    // ======== phase C : accept/reject + FSAL copy (CTA = batch) ========
    {
      const float t = scal[0], dtv = scal[1], dt_c = scal[2];
      float k7v = 0.f;
      if (tid < NH) {
        int h = tid;
        float k1 = __ldcg(&g_k[0][bid*NH+h]);
        float k3 = __ldcg(&g_k[2][bid*NH+h]);
        float k4 = __ldcg(&g_k[3][bid*NH+h]);
        float k5 = __ldcg(&g_k[4][bid*NH+h]);
        float k6 = __ldcg(&g_k[5][bid*NH+h]);
        float k7 = __ldcg(&g_k[6][bid*NH+h]);
        k7v = k7;
        float y  = g_Y[bid*NH+h];
        float yn = g_ynew[bid*NH+h];
        float ev = dt_c * (E0*k1 + E2*k3 + E3*k4 + E4*k5 + E5*k6 + E6*k7);
        float sc = 1e-3f + 1e-3f * fmaxf(fabsf(y), fabsf(yn));
        float e = ev / sc;
        float e2v = e*e;
        #pragma unroll
        for (int o = 16; o > 0; o >>= 1) e2v += __shfl_down_sync(0xffffffffu, e2v, o);
        if ((tid & 31) == 0) red[tid >> 5] = e2v;
      }
      __syncthreads();
      if (tid == 0) {
        float ssum = red[0] + red[1] + red[2] + red[3];
        float err = sqrtf(ssum * (1.f/(float)NH));
        bool accept = (err <= 1.0f);
        float fac = 0.9f * powf(fmaxf(err, 1e-9f), -0.2f);
        fac = fminf(fmaxf(fac, 0.2f), 10.f);
        bool done = (t >= tEnd - 1e-8f);
        bool adv = accept && !done;
        float t_new = adv ? (t + dt_c) : t;
        g_t[bid]  = t_new;
        g_dt[bid] = done ? dtv : (dt_c * fac);
        scal[3] = adv ? 1.f : 0.f;
        if (!counted && t_new >= tEnd - 1e-8f) {
          atomicAdd(&g_ndone, 1u);
          counted = true;
        }
      }
      __syncthreads();
      if (tid < NH && scal[3] != 0.f) {
        g_Y[bid*NH + tid] = g_ynew[bid*NH + tid];
        __stcg(&g_k[0][bid*NH + tid], k7v);   // FSAL
      }
      __syncthreads();
    }
  }

  if (tid < NO) {
    float acc = lin_b[tid];
    #pragma unroll 4
    for (int h = 0; h < NH; h++)
      acc = fmaf(lin_w[tid*NH + h], g_Y[bid*NH + h], acc);
    out[bid*NO + tid] = acc;
  }
}

extern "C" void kernel_launch(void* const* d_in, const int* in_sizes, int n_in,
                              void* d_out, int out_size) {
  const float* ts    = (const float*)d_in[0];
  const float* xs    = (const float*)d_in[1];
  const float* W1    = (const float*)d_in[2];
  const float* b1    = (const float*)d_in[3];
  const float* W2    = (const float*)d_in[4];
  const float* b2    = (const float*)d_in[5];
  const float* lin_w = (const float*)d_in[6];
  const float* lin_b = (const float*)d_in[7];
  float* out = (float*)d_out;
  cudaFuncSetAttribute(cde_kernel, cudaFuncAttributeMaxDynamicSharedMemorySize, SMEM_BYTES);
  cde_kernel<<<NCTA, NTHR, SMEM_BYTES>>>(ts, xs, W1, b1, W2, b2, lin_w, lin_b, out);
}

// round 10
// speedup vs baseline: 52.2953x; 1.0272x over previous
#include <cuda_runtime.h>
#include <cuda_bf16.h>
#include <cstdint>

#define NB 128
#define NT 128
#define NC 32
#define NH 128
#define NO 10
#define NCTA 128
#define NTHR 256
#define MAXSTEPS 64

// ---- smem layout (float offsets) ----
#define W1PR 132
#define W2PR 68
#define H1PR 68
#define DXPR 36
#define OFF_W1S 0            // 128*132 = 16896
#define OFF_W2HI 16896       // 2176 u32
#define OFF_W2LO 19072       // 2176 u32
#define OFF_H1HI 21248       // 8704 u32
#define OFF_H1LO 29952       // 8704 u32
#define OFF_DXS 38656        // 128*36 = 4608
#define OFF_RED 43264        // 256
#define OFF_TS  43520        // 128
#define OFF_B1  43648        // 128
#define OFF_B2  43776       // 32
#define OFF_YS  43808        // 128
#define OFF_YC  43936        // 128
#define OFF_SC  44064        // 8
#define SMEM_FLOATS 44072
#define SMEM_BYTES (SMEM_FLOATS * 4)   // 176288 B

__device__ __align__(16) float g_k[7][NB*NH];
__device__ __align__(16) unsigned g_H1hi[NB*64];
__device__ __align__(16) unsigned g_H1lo[NB*64];
__device__ __align__(16) float g_dX[NB*NC];
__device__ __align__(128) unsigned g_flags[NCTA*32];
__device__ unsigned g_ndone;

__constant__ float A_TAB[7][6] = {
  {0.f,0.f,0.f,0.f,0.f,0.f},
  {(float)(1.0/5.0),0.f,0.f,0.f,0.f,0.f},
  {(float)(3.0/40.0),(float)(9.0/40.0),0.f,0.f,0.f,0.f},
  {(float)(44.0/45.0),(float)(-56.0/15.0),(float)(32.0/9.0),0.f,0.f,0.f},
  {(float)(19372.0/6561.0),(float)(-25360.0/2187.0),(float)(64448.0/6561.0),(float)(-212.0/729.0),0.f,0.f},
  {(float)(9017.0/3168.0),(float)(-355.0/33.0),(float)(46732.0/5247.0),(float)(49.0/176.0),(float)(-5103.0/18656.0),0.f},
  {(float)(35.0/384.0),0.f,(float)(500.0/1113.0),(float)(125.0/192.0),(float)(-2187.0/6784.0),(float)(11.0/84.0)},
};
__constant__ float C_TAB[7] = {0.f,(float)(1.0/5.0),(float)(3.0/10.0),(float)(4.0/5.0),(float)(8.0/9.0),1.f,1.f};

#define E0 ((float)(71.0/57600.0))
#define E2 ((float)(-71.0/16695.0))
#define E3 ((float)(71.0/1920.0))
#define E4 ((float)(-17253.0/339200.0))
#define E5 ((float)(22.0/525.0))
#define E6 ((float)(-1.0/40.0))

__device__ __forceinline__ unsigned ld_u32_cg(const unsigned* p) {
  unsigned v; asm volatile("ld.global.cg.u32 %0, [%1];" : "=r"(v) : "l"(p)); return v;
}
__device__ __forceinline__ void st_u32_cg(unsigned* p, unsigned v) {
  asm volatile("st.global.cg.u32 [%0], %1;" :: "l"(p), "r"(v) : "memory");
}
__device__ __forceinline__ float fast_tanh(float x) {
  x = fminf(fmaxf(x, -9.f), 9.f);
  float e = __expf(2.f * x);
  return __fdividef(e - 1.f, e + 1.f);
}
__device__ __forceinline__ uint32_t pack_bf16x2(float e0, float e1) {
  uint32_t d;
  asm("cvt.rn.bf16x2.f32 %0, %1, %2;" : "=r"(d) : "f"(e1), "f"(e0));
  return d;
}
__device__ __forceinline__ uint32_t smem_u32(const void* p) {
  uint32_t a;
  asm("{ .reg .u64 t; cvta.to.shared.u64 t, %1; cvt.u32.u64 %0, t; }" : "=r"(a) : "l"(p));
  return a;
}
__device__ __forceinline__ void mma_bf16(float* d, uint32_t a0, uint32_t a1, uint32_t a2, uint32_t a3,
                                         uint32_t b0, uint32_t b1) {
  asm volatile(
    "mma.sync.aligned.m16n8k16.row.col.f32.bf16.bf16.f32 "
    "{%0,%1,%2,%3}, {%4,%5,%6,%7}, {%8,%9}, {%0,%1,%2,%3};"
    : "+f"(d[0]), "+f"(d[1]), "+f"(d[2]), "+f"(d[3])
    : "r"(a0), "r"(a1), "r"(a2), "r"(a3), "r"(b0), "r"(b1));
}
__device__ __forceinline__ void ldmx4(uint32_t* r, uint32_t addr) {
  asm volatile("ldmatrix.sync.aligned.m8n8.x4.shared.b16 {%0,%1,%2,%3}, [%4];"
    : "=r"(r[0]), "=r"(r[1]), "=r"(r[2]), "=r"(r[3]) : "r"(addr));
}

// all-poll distributed barrier (monotone seq, replay-safe)
__device__ __forceinline__ void gbar(unsigned seq) {
  __syncthreads();
  const int tid = threadIdx.x;
  if (tid == 0) {
    __threadfence();
    st_u32_cg(&g_flags[blockIdx.x * 32], seq);
  }
  if (tid < NCTA) {
    while ((int)(ld_u32_cg(&g_flags[tid * 32]) - seq) < 0) { }
  }
  __threadfence();
  __syncthreads();
}

__global__ __launch_bounds__(NTHR, 1)
void cde_kernel(const float* __restrict__ ts, const float* __restrict__ xs,
                const float* __restrict__ W1, const float* __restrict__ b1,
                const float* __restrict__ W2, const float* __restrict__ b2,
                const float* __restrict__ lin_w, const float* __restrict__ lin_b,
                float* __restrict__ out)
{
  extern __shared__ float sm[];
  float*    W1s  = sm + OFF_W1S;     // [h][k] pad 132
  unsigned* W2hiS= (unsigned*)(sm + OFF_W2HI);
  unsigned* W2loS= (unsigned*)(sm + OFF_W2LO);
  unsigned* H1hiS= (unsigned*)(sm + OFF_H1HI);
  unsigned* H1loS= (unsigned*)(sm + OFF_H1LO);
  float*    dXs  = sm + OFF_DXS;
  float*    red  = sm + OFF_RED;
  float*    tss  = sm + OFF_TS;
  float*    b1s  = sm + OFF_B1;
  float*    b2s  = sm + OFF_B2;
  float*    Ysm  = sm + OFF_YS;
  float*    Ycur = sm + OFF_YC;
  float*    scal = sm + OFF_SC;

  const int tid = threadIdx.x;
  const int bid = blockIdx.x;
  const int wid = tid >> 5;
  const int lane = tid & 31;
  const int g = lane >> 2;
  const int q = lane & 3;
  const uint32_t smb = smem_u32(sm);

  const unsigned base_nd = ld_u32_cg(&g_ndone);
  unsigned seq = ld_u32_cg(&g_flags[bid * 32]);

  // ---- one-time setup ----
  for (int i = tid; i < NH*NH; i += NTHR) { int h = i >> 7, k = i & 127; W1s[h*W1PR + k] = W1[i]; }
  for (int i = tid; i < 32*64; i += NTHR) {
    int c = i >> 6, kq = i & 63;
    float w0 = W2[bid*32*NH + c*NH + kq*2];
    float w1 = W2[bid*32*NH + c*NH + kq*2 + 1];
    __nv_bfloat16 h0 = __float2bfloat16(w0), h1 = __float2bfloat16(w1);
    W2hiS[c*W2PR + kq] = pack_bf16x2(w0, w1);
    W2loS[c*W2PR + kq] = pack_bf16x2(w0 - __bfloat162float(h0), w1 - __bfloat162float(h1));
  }
  for (int i = tid; i < NT; i += NTHR) tss[i] = ts[i];
  for (int i = tid; i < NH; i += NTHR) b1s[i] = b1[i];
  if (tid < 32) b2s[tid] = b2[bid*32 + tid];
  if (tid < NH) Ycur[tid] = 0.f;
  if (tid == 0) {
    float t0 = ts[0], te = ts[NT-1];
    scal[0] = t0; scal[1] = 0.01f; scal[2] = fminf(0.01f, te - t0);
  }
  __syncthreads();
  const float tEnd = tss[NT-1];
  const float* xb = xs + (size_t)bid*NT*NC;

  const int lrow = wid*16 + (lane & 7) + ((lane >> 3) & 1) * 8;
  const int lcol = ((lane >> 4) & 1) * 4;
  const uint32_t hibase = smb + (uint32_t)(OFF_H1HI + lrow*H1PR + lcol) * 4u;
  const uint32_t lobase = smb + (uint32_t)(OFF_H1LO + lrow*H1PR + lcol) * 4u;

  float yreg = 0.f;      // own y[h=tid] (tid<128)
  float ynew_r = 0.f;    // y_new[h=tid]
  bool counted = false;
  bool exit_all = false;

  for (int step = 0; step < MAXSTEPS && !exit_all; step++) {
    const int sb = (step == 0) ? 0 : 1;   // FSAL
    const float tcur = scal[0];
    const float dt_c = scal[2];
    for (int s = sb; s < 7; s++) {
      // ======== phase A : CTA = batch ========
      if (tid < NH) {
        float ysv;
        if (s == 0) ysv = yreg;
        else {
          float acc = 0.f;
          for (int j = 0; j < s; j++)
            acc += A_TAB[s][j] * __ldcg(&g_k[j][bid*NH + tid]);
          ysv = yreg + dt_c * acc;
        }
        Ysm[tid] = ysv;
        if (s == 6) ynew_r = ysv;
      } else if (tid < NH + NC) {
        int c = tid - NH;
        float tq = tcur + C_TAB[s] * dt_c;
        int lo = 0, hi = NT;
        while (lo < hi) { int mid = (lo + hi) >> 1; if (tss[mid] <= tq) lo = mid + 1; else hi = mid; }
        int idx = lo - 1; if (idx < 0) idx = 0; if (idx > NT-2) idx = NT-2;
        float t0 = tss[idx], t1 = tss[idx+1];
        float hh = t1 - t0;
        float sfr = (tq - t0) / hh;
        float dh00 = 6.f*sfr*sfr - 6.f*sfr;
        float dh10 = 3.f*sfr*sfr - 4.f*sfr + 1.f;
        float dh11 = 3.f*sfr*sfr - 2.f*sfr;
        float x0 = __ldg(&xb[idx*NC + c]);
        float x1 = __ldg(&xb[(idx+1)*NC + c]);
        float mi1 = (x1 - x0) / hh;
        float mi;
        if (idx == 0) mi = (x1 - x0) / (tss[1] - tss[0]);
        else { float xm1 = __ldg(&xb[(idx-1)*NC + c]); mi = (x0 - xm1) / (tss[idx] - tss[idx-1]); }
        float dx = (dh00*x0 - dh00*x1) / hh + dh10*mi + dh11*mi1;
        __stcg(&g_dX[bid*NC + c], dx);
      }
      __syncthreads();
      {
        int h = tid & 127;
        int half = tid >> 7;
        const int kb = half * 64;
        float a0=0.f,a1=0.f,a2=0.f,a3=0.f;
        const float* wrow = &W1s[h*W1PR + kb];
        #pragma unroll 4
        for (int k = 0; k < 64; k += 4) {
          float4 wv = *(const float4*)&wrow[k];
          float4 yv = *(const float4*)&Ysm[kb + k];
          a0 = fmaf(wv.x, yv.x, a0);
          a1 = fmaf(wv.y, yv.y, a1);
          a2 = fmaf(wv.z, yv.z, a2);
          a3 = fmaf(wv.w, yv.w, a3);
        }
        red[half*NH + h] = (a0+a1)+(a2+a3);
      }
      __syncthreads();
      if (tid < 64) {
        float f0 = fmaxf(b1s[2*tid]   + red[2*tid]   + red[NH + 2*tid],   0.f);
        float f1 = fmaxf(b1s[2*tid+1] + red[2*tid+1] + red[NH + 2*tid+1], 0.f);
        uint32_t hi = pack_bf16x2(f0, f1);
        __nv_bfloat162 hb = *reinterpret_cast<__nv_bfloat162*>(&hi);
        uint32_t lo = pack_bf16x2(f0 - __bfloat162float(hb.x), f1 - __bfloat162float(hb.y));
        st_u32_cg(&g_H1hi[bid*64 + tid], hi);
        st_u32_cg(&g_H1lo[bid*64 + tid], lo);
      }
      gbar(++seq);

      if (s == sb) {
        if (tid == 0) scal[4] = (float)(ld_u32_cg(&g_ndone) - base_nd);
        __syncthreads();
        if (scal[4] == (float)NB) { exit_all = true; break; }
      }

      // ======== phase B : CTA = h-group, ldmatrix + bf16 HMMA ========
      {
        for (int i = tid; i < 128*16; i += NTHR) {
          int row = i >> 4, c4 = (i & 15) * 4;
          uint4 u = __ldcg((const uint4*)&g_H1hi[row*64 + c4]);
          *(uint4*)&H1hiS[row*H1PR + c4] = u;
          uint4 v = __ldcg((const uint4*)&g_H1lo[row*64 + c4]);
          *(uint4*)&H1loS[row*H1PR + c4] = v;
        }
        for (int i = tid; i < (NB*NC)/4; i += NTHR) {
          int b = i >> 3, c4 = (i & 7) * 4;
          float4 u = __ldcg((const float4*)&g_dX[b*NC + c4]);
          *(float4*)&dXs[b*DXPR + c4] = u;
        }
        __syncthreads();

        const int mb = wid * 16;
        float d[4][4];
        #pragma unroll
        for (int nt = 0; nt < 4; nt++)
          #pragma unroll
          for (int r = 0; r < 4; r++) d[nt][r] = 0.f;

        #pragma unroll
        for (int kk = 0; kk < 8; kk++) {
          const int kq = kk*8 + q;
          uint32_t ah[4], al[4];
          ldmx4(ah, hibase + (uint32_t)kk * 32u);
          ldmx4(al, lobase + (uint32_t)kk * 32u);
          #pragma unroll
          for (int nt = 0; nt < 4; nt++) {
            const int c = nt*8 + g;
            uint32_t bh0 = W2hiS[c*W2PR + kq];
            uint32_t bh1 = W2hiS[c*W2PR + kq + 4];
            uint32_t bl0 = W2loS[c*W2PR + kq];
            uint32_t bl1 = W2loS[c*W2PR + kq + 4];
            mma_bf16(d[nt], ah[0], ah[1], ah[2], ah[3], bh0, bh1);
            mma_bf16(d[nt], al[0], al[1], al[2], al[3], bh0, bh1);
            mma_bf16(d[nt], ah[0], ah[1], ah[2], ah[3], bl0, bl1);
          }
        }

        float part0 = 0.f, part1 = 0.f;
        const int row0 = mb + g, row1 = mb + g + 8;
        #pragma unroll
        for (int nt = 0; nt < 4; nt++) {
          const int cb = nt*8 + q*2;
          float bb0 = b2s[cb], bb1 = b2s[cb+1];
          part0 += fast_tanh(d[nt][0] + bb0) * dXs[row0*DXPR + cb]
                 + fast_tanh(d[nt][1] + bb1) * dXs[row0*DXPR + cb + 1];
          part1 += fast_tanh(d[nt][2] + bb0) * dXs[row1*DXPR + cb]
                 + fast_tanh(d[nt][3] + bb1) * dXs[row1*DXPR + cb + 1];
        }
        part0 += __shfl_xor_sync(0xffffffffu, part0, 1);
        part0 += __shfl_xor_sync(0xffffffffu, part0, 2);
        part1 += __shfl_xor_sync(0xffffffffu, part1, 1);
        part1 += __shfl_xor_sync(0xffffffffu, part1, 2);
        if (q == 0) {
          __stcg(&g_k[s][row0*NH + bid], part0);
          __stcg(&g_k[s][row1*NH + bid], part1);
        }
      }
      gbar(++seq);
    }
    if (exit_all) break;

    // ======== phase C : accept/reject + FSAL + next-step scal ========
    {
      const float t = tcur, dtv = scal[1];
      float k7v = 0.f;
      if (tid < NH) {
        int h = tid;
        float k1 = __ldcg(&g_k[0][bid*NH+h]);
        float k3 = __ldcg(&g_k[2][bid*NH+h]);
        float k4 = __ldcg(&g_k[3][bid*NH+h]);
        float k5 = __ldcg(&g_k[4][bid*NH+h]);
        float k6 = __ldcg(&g_k[5][bid*NH+h]);
        float k7 = __ldcg(&g_k[6][bid*NH+h]);
        k7v = k7;
        float ev = dt_c * (E0*k1 + E2*k3 + E3*k4 + E4*k5 + E5*k6 + E6*k7);
        float sc = 1e-3f + 1e-3f * fmaxf(fabsf(yreg), fabsf(ynew_r));
        float e = ev / sc;
        float e2v = e*e;
        #pragma unroll
        for (int o = 16; o > 0; o >>= 1) e2v += __shfl_down_sync(0xffffffffu, e2v, o);
        if ((tid & 31) == 0) red[tid >> 5] = e2v;
      }
      __syncthreads();
      if (tid == 0) {
        float ssum = red[0] + red[1] + red[2] + red[3];
        float err = sqrtf(ssum * (1.f/(float)NH));
        bool accept = (err <= 1.0f);
        float fac = 0.9f * powf(fmaxf(err, 1e-9f), -0.2f);
        fac = fminf(fmaxf(fac, 0.2f), 10.f);
        bool done = (t >= tEnd - 1e-8f);
        bool adv = accept && !done;
        float t_new = adv ? (t + dt_c) : t;
        float dt_new = done ? dtv : (dt_c * fac);
        scal[0] = t_new;
        scal[1] = dt_new;
        scal[2] = fminf(dt_new, tEnd - t_new);
        scal[3] = adv ? 1.f : 0.f;
        if (!counted && t_new >= tEnd - 1e-8f) {
          atomicAdd(&g_ndone, 1u);
          counted = true;
        }
      }
      __syncthreads();
      if (tid < NH && scal[3] != 0.f) {
        yreg = ynew_r;
        Ycur[tid] = ynew_r;
        __stcg(&g_k[0][bid*NH + tid], k7v);   // FSAL
      }
      __syncthreads();
    }
  }

  if (tid < NO) {
    float acc = lin_b[tid];
    #pragma unroll 4
    for (int h = 0; h < NH; h++)
      acc = fmaf(lin_w[tid*NH + h], Ycur[h], acc);
    out[bid*NO + tid] = acc;
  }
}

extern "C" void kernel_launch(void* const* d_in, const int* in_sizes, int n_in,
                              void* d_out, int out_size) {
  const float* ts    = (const float*)d_in[0];
  const float* xs    = (const float*)d_in[1];
  const float* W1    = (const float*)d_in[2];
  const float* b1    = (const float*)d_in[3];
  const float* W2    = (const float*)d_in[4];
  const float* b2    = (const float*)d_in[5];
  const float* lin_w = (const float*)d_in[6];
  const float* lin_b = (const float*)d_in[7];
  float* out = (float*)d_out;
  cudaFuncSetAttribute(cde_kernel, cudaFuncAttributeMaxDynamicSharedMemorySize, SMEM_BYTES);
  cde_kernel<<<NCTA, NTHR, SMEM_BYTES>>>(ts, xs, W1, b1, W2, b2, lin_w, lin_b, out);
}

// round 11
// speedup vs baseline: 53.7672x; 1.0281x over previous
#include <cuda_runtime.h>
#include <cuda_bf16.h>
#include <cstdint>

#define NB 128
#define NT 128
#define NC 32
#define NH 128
#define NO 10
#define NCTA 128
#define NTHR 256
#define MAXSTEPS 64

// ---- smem layout (float offsets) ----
#define W1PR 132
#define W2PR 68
#define H1PR 68
#define DXPR 36
#define OFF_W1S 0            // 128*132 = 16896
#define OFF_W2HI 16896       // 2176 u32
#define OFF_W2LO 19072       // 2176 u32
#define OFF_H1HI 21248       // 8704 u32
#define OFF_H1LO 29952       // 8704 u32
#define OFF_DXS 38656        // 128*36 = 4608
#define OFF_RED 43264        // 256
#define OFF_TS  43520        // 128
#define OFF_B1  43648        // 128
#define OFF_B2  43776        // 32
#define OFF_YS  43808        // 128
#define OFF_YC  43936        // 128
#define OFF_SC  44064        // 8
#define SMEM_FLOATS 44072
#define SMEM_BYTES (SMEM_FLOATS * 4)   // 176288 B

__device__ __align__(16) float g_k[7][NB*NH];
__device__ __align__(16) unsigned g_H1hi[NB*64];
__device__ __align__(16) unsigned g_H1lo[NB*64];
__device__ __align__(16) float g_dX[7][NB*NC];
__device__ __align__(128) unsigned g_flags[NCTA*32];
__device__ unsigned g_ndone;

__constant__ float A_TAB[7][6] = {
  {0.f,0.f,0.f,0.f,0.f,0.f},
  {(float)(1.0/5.0),0.f,0.f,0.f,0.f,0.f},
  {(float)(3.0/40.0),(float)(9.0/40.0),0.f,0.f,0.f,0.f},
  {(float)(44.0/45.0),(float)(-56.0/15.0),(float)(32.0/9.0),0.f,0.f,0.f},
  {(float)(19372.0/6561.0),(float)(-25360.0/2187.0),(float)(64448.0/6561.0),(float)(-212.0/729.0),0.f,0.f},
  {(float)(9017.0/3168.0),(float)(-355.0/33.0),(float)(46732.0/5247.0),(float)(49.0/176.0),(float)(-5103.0/18656.0),0.f},
  {(float)(35.0/384.0),0.f,(float)(500.0/1113.0),(float)(125.0/192.0),(float)(-2187.0/6784.0),(float)(11.0/84.0)},
};
__constant__ float C_TAB[7] = {0.f,(float)(1.0/5.0),(float)(3.0/10.0),(float)(4.0/5.0),(float)(8.0/9.0),1.f,1.f};

#define E0 ((float)(71.0/57600.0))
#define E2 ((float)(-71.0/16695.0))
#define E3 ((float)(71.0/1920.0))
#define E4 ((float)(-17253.0/339200.0))
#define E5 ((float)(22.0/525.0))
#define E6 ((float)(-1.0/40.0))

__device__ __forceinline__ unsigned ld_u32_cg(const unsigned* p) {
  unsigned v; asm volatile("ld.global.cg.u32 %0, [%1];" : "=r"(v) : "l"(p)); return v;
}
__device__ __forceinline__ void st_u32_cg(unsigned* p, unsigned v) {
  asm volatile("st.global.cg.u32 [%0], %1;" :: "l"(p), "r"(v) : "memory");
}
__device__ __forceinline__ float fast_tanh(float x) {
  x = fminf(fmaxf(x, -9.f), 9.f);
  float e = __expf(2.f * x);
  return __fdividef(e - 1.f, e + 1.f);
}
__device__ __forceinline__ uint32_t pack_bf16x2(float e0, float e1) {
  uint32_t d;
  asm("cvt.rn.bf16x2.f32 %0, %1, %2;" : "=r"(d) : "f"(e1), "f"(e0));
  return d;
}
__device__ __forceinline__ uint32_t smem_u32(const void* p) {
  uint32_t a;
  asm("{ .reg .u64 t; cvta.to.shared.u64 t, %1; cvt.u32.u64 %0, t; }" : "=r"(a) : "l"(p));
  return a;
}
__device__ __forceinline__ void mma_bf16(float* d, uint32_t a0, uint32_t a1, uint32_t a2, uint32_t a3,
                                         uint32_t b0, uint32_t b1) {
  asm volatile(
    "mma.sync.aligned.m16n8k16.row.col.f32.bf16.bf16.f32 "
    "{%0,%1,%2,%3}, {%4,%5,%6,%7}, {%8,%9}, {%0,%1,%2,%3};"
    : "+f"(d[0]), "+f"(d[1]), "+f"(d[2]), "+f"(d[3])
    : "r"(a0), "r"(a1), "r"(a2), "r"(a3), "r"(b0), "r"(b1));
}
__device__ __forceinline__ void ldmx4(uint32_t* r, uint32_t addr) {
  asm volatile("ldmatrix.sync.aligned.m8n8.x4.shared.b16 {%0,%1,%2,%3}, [%4];"
    : "=r"(r[0]), "=r"(r[1]), "=r"(r[2]), "=r"(r[3]) : "r"(addr));
}

// all-poll distributed barrier (monotone seq, replay-safe)
__device__ __forceinline__ void gbar(unsigned seq) {
  __syncthreads();
  const int tid = threadIdx.x;
  if (tid == 0) {
    __threadfence();
    st_u32_cg(&g_flags[blockIdx.x * 32], seq);
  }
  if (tid < NCTA) {
    while ((int)(ld_u32_cg(&g_flags[tid * 32]) - seq) < 0) { }
  }
  __threadfence();
  __syncthreads();
}

__global__ __launch_bounds__(NTHR, 1)
void cde_kernel(const float* __restrict__ ts, const float* __restrict__ xs,
                const float* __restrict__ W1, const float* __restrict__ b1,
                const float* __restrict__ W2, const float* __restrict__ b2,
                const float* __restrict__ lin_w, const float* __restrict__ lin_b,
                float* __restrict__ out)
{
  extern __shared__ float sm[];
  float*    W1s  = sm + OFF_W1S;
  unsigned* W2hiS= (unsigned*)(sm + OFF_W2HI);
  unsigned* W2loS= (unsigned*)(sm + OFF_W2LO);
  unsigned* H1hiS= (unsigned*)(sm + OFF_H1HI);
  unsigned* H1loS= (unsigned*)(sm + OFF_H1LO);
  float*    dXs  = sm + OFF_DXS;
  float*    red  = sm + OFF_RED;
  float*    tss  = sm + OFF_TS;
  float*    b1s  = sm + OFF_B1;
  float*    b2s  = sm + OFF_B2;
  float*    Ysm  = sm + OFF_YS;
  float*    Ycur = sm + OFF_YC;
  float*    scal = sm + OFF_SC;

  const int tid = threadIdx.x;
  const int bid = blockIdx.x;
  const int wid = tid >> 5;
  const int lane = tid & 31;
  const int g = lane >> 2;
  const int q = lane & 3;
  const uint32_t smb = smem_u32(sm);

  const unsigned base_nd = ld_u32_cg(&g_ndone);
  unsigned seq = ld_u32_cg(&g_flags[bid * 32]);

  // ---- one-time setup ----
  for (int i = tid; i < NH*NH; i += NTHR) { int h = i >> 7, k = i & 127; W1s[h*W1PR + k] = W1[i]; }
  for (int i = tid; i < 32*64; i += NTHR) {
    int c = i >> 6, kq = i & 63;
    float w0 = W2[bid*32*NH + c*NH + kq*2];
    float w1 = W2[bid*32*NH + c*NH + kq*2 + 1];
    __nv_bfloat16 h0 = __float2bfloat16(w0), h1 = __float2bfloat16(w1);
    W2hiS[c*W2PR + kq] = pack_bf16x2(w0, w1);
    W2loS[c*W2PR + kq] = pack_bf16x2(w0 - __bfloat162float(h0), w1 - __bfloat162float(h1));
  }
  for (int i = tid; i < NT; i += NTHR) tss[i] = ts[i];
  for (int i = tid; i < NH; i += NTHR) b1s[i] = b1[i];
  if (tid < 32) b2s[tid] = b2[bid*32 + tid];
  if (tid < NH) Ycur[tid] = 0.f;
  if (tid == 0) {
    float t0 = ts[0], te = ts[NT-1];
    scal[0] = t0; scal[1] = 0.01f; scal[2] = fminf(0.01f, te - t0);
  }
  __syncthreads();
  const float tEnd = tss[NT-1];
  const float* xb = xs + (size_t)bid*NT*NC;

  const int lrow = wid*16 + (lane & 7) + ((lane >> 3) & 1) * 8;
  const int lcol = ((lane >> 4) & 1) * 4;
  const uint32_t hibase = smb + (uint32_t)(OFF_H1HI + lrow*H1PR + lcol) * 4u;
  const uint32_t lobase = smb + (uint32_t)(OFF_H1LO + lrow*H1PR + lcol) * 4u;

  float yreg = 0.f;
  float ynew_r = 0.f;
  bool counted = false;
  bool exit_all = false;

  for (int step = 0; step < MAXSTEPS && !exit_all; step++) {
    const int sb = (step == 0) ? 0 : 1;   // FSAL
    const float tcur = scal[0];
    const float dt_c = scal[2];
    for (int s = sb; s < 7; s++) {
      // ======== phase A : CTA = batch ========
      if (s > sb) {
        // stage this stage's dX into SMEM (visible since step's first barrier)
        for (int i = tid; i < (NB*NC)/4; i += NTHR) {
          int b = i >> 3, c4 = (i & 7) * 4;
          float4 u = __ldcg((const float4*)&g_dX[s][b*NC + c4]);
          *(float4*)&dXs[b*DXPR + c4] = u;
        }
      }
      if (tid < NH) {
        float ysv;
        if (s == 0) ysv = yreg;
        else {
          float acc = 0.f;
          for (int j = 0; j < s; j++)
            acc += A_TAB[s][j] * __ldcg(&g_k[j][bid*NH + tid]);
          ysv = yreg + dt_c * acc;
        }
        Ysm[tid] = ysv;
        if (s == 6) ynew_r = ysv;
      } else if (s == sb) {
        // compute dX for ALL stages of this step (t, dt_c known)
        for (int i = tid - 128; i < (7 - sb) * NC; i += 128) {
          int sp = sb + i / NC;
          int c = i % NC;
          float tq = tcur + C_TAB[sp] * dt_c;
          int lo = 0, hi = NT;
          while (lo < hi) { int mid = (lo + hi) >> 1; if (tss[mid] <= tq) lo = mid + 1; else hi = mid; }
          int idx = lo - 1; if (idx < 0) idx = 0; if (idx > NT-2) idx = NT-2;
          float t0 = tss[idx], t1 = tss[idx+1];
          float hh = t1 - t0;
          float sfr = (tq - t0) / hh;
          float dh00 = 6.f*sfr*sfr - 6.f*sfr;
          float dh10 = 3.f*sfr*sfr - 4.f*sfr + 1.f;
          float dh11 = 3.f*sfr*sfr - 2.f*sfr;
          float x0 = __ldg(&xb[idx*NC + c]);
          float x1 = __ldg(&xb[(idx+1)*NC + c]);
          float mi1 = (x1 - x0) / hh;
          float mi;
          if (idx == 0) mi = (x1 - x0) / (tss[1] - tss[0]);
          else { float xm1 = __ldg(&xb[(idx-1)*NC + c]); mi = (x0 - xm1) / (tss[idx] - tss[idx-1]); }
          float dx = (dh00*x0 - dh00*x1) / hh + dh10*mi + dh11*mi1;
          __stcg(&g_dX[sp][bid*NC + c], dx);
        }
      }
      __syncthreads();
      {
        int h = tid & 127;
        int half = tid >> 7;
        const int kb = half * 64;
        float a0=0.f,a1=0.f,a2=0.f,a3=0.f;
        const float* wrow = &W1s[h*W1PR + kb];
        #pragma unroll 4
        for (int k = 0; k < 64; k += 4) {
          float4 wv = *(const float4*)&wrow[k];
          float4 yv = *(const float4*)&Ysm[kb + k];
          a0 = fmaf(wv.x, yv.x, a0);
          a1 = fmaf(wv.y, yv.y, a1);
          a2 = fmaf(wv.z, yv.z, a2);
          a3 = fmaf(wv.w, yv.w, a3);
        }
        red[half*NH + h] = (a0+a1)+(a2+a3);
      }
      __syncthreads();
      if (tid < 64) {
        float f0 = fmaxf(b1s[2*tid]   + red[2*tid]   + red[NH + 2*tid],   0.f);
        float f1 = fmaxf(b1s[2*tid+1] + red[2*tid+1] + red[NH + 2*tid+1], 0.f);
        uint32_t hi = pack_bf16x2(f0, f1);
        __nv_bfloat162 hb = *reinterpret_cast<__nv_bfloat162*>(&hi);
        uint32_t lo = pack_bf16x2(f0 - __bfloat162float(hb.x), f1 - __bfloat162float(hb.y));
        st_u32_cg(&g_H1hi[bid*64 + tid], hi);
        st_u32_cg(&g_H1lo[bid*64 + tid], lo);
      }
      gbar(++seq);

      if (s == sb) {
        if (tid == 0) scal[4] = (float)(ld_u32_cg(&g_ndone) - base_nd);
        __syncthreads();
        if (scal[4] == (float)NB) { exit_all = true; break; }
      }

      // ======== phase B : CTA = h, ldmatrix + bf16 HMMA ========
      {
        for (int i = tid; i < 128*16; i += NTHR) {
          int row = i >> 4, c4 = (i & 15) * 4;
          uint4 u = __ldcg((const uint4*)&g_H1hi[row*64 + c4]);
          *(uint4*)&H1hiS[row*H1PR + c4] = u;
          uint4 v = __ldcg((const uint4*)&g_H1lo[row*64 + c4]);
          *(uint4*)&H1loS[row*H1PR + c4] = v;
        }
        if (s == sb) {
          for (int i = tid; i < (NB*NC)/4; i += NTHR) {
            int b = i >> 3, c4 = (i & 7) * 4;
            float4 u = __ldcg((const float4*)&g_dX[s][b*NC + c4]);
            *(float4*)&dXs[b*DXPR + c4] = u;
          }
        }
        __syncthreads();

        const int mb = wid * 16;
        float d[4][4];
        #pragma unroll
        for (int nt = 0; nt < 4; nt++)
          #pragma unroll
          for (int r = 0; r < 4; r++) d[nt][r] = 0.f;

        #pragma unroll
        for (int kk = 0; kk < 8; kk++) {
          const int kq = kk*8 + q;
          uint32_t ah[4], al[4];
          ldmx4(ah, hibase + (uint32_t)kk * 32u);
          ldmx4(al, lobase + (uint32_t)kk * 32u);
          #pragma unroll
          for (int nt = 0; nt < 4; nt++) {
            const int c = nt*8 + g;
            uint32_t bh0 = W2hiS[c*W2PR + kq];
            uint32_t bh1 = W2hiS[c*W2PR + kq + 4];
            uint32_t bl0 = W2loS[c*W2PR + kq];
            uint32_t bl1 = W2loS[c*W2PR + kq + 4];
            mma_bf16(d[nt], ah[0], ah[1], ah[2], ah[3], bh0, bh1);
            mma_bf16(d[nt], al[0], al[1], al[2], al[3], bh0, bh1);
            mma_bf16(d[nt], ah[0], ah[1], ah[2], ah[3], bl0, bl1);
          }
        }

        float part0 = 0.f, part1 = 0.f;
        const int row0 = mb + g, row1 = mb + g + 8;
        #pragma unroll
        for (int nt = 0; nt < 4; nt++) {
          const int cb = nt*8 + q*2;
          float bb0 = b2s[cb], bb1 = b2s[cb+1];
          part0 += fast_tanh(d[nt][0] + bb0) * dXs[row0*DXPR + cb]
                 + fast_tanh(d[nt][1] + bb1) * dXs[row0*DXPR + cb + 1];
          part1 += fast_tanh(d[nt][2] + bb0) * dXs[row1*DXPR + cb]
                 + fast_tanh(d[nt][3] + bb1) * dXs[row1*DXPR + cb + 1];
        }
        part0 += __shfl_xor_sync(0xffffffffu, part0, 1);
        part0 += __shfl_xor_sync(0xffffffffu, part0, 2);
        part1 += __shfl_xor_sync(0xffffffffu, part1, 1);
        part1 += __shfl_xor_sync(0xffffffffu, part1, 2);
        if (q == 0) {
          __stcg(&g_k[s][row0*NH + bid], part0);
          __stcg(&g_k[s][row1*NH + bid], part1);
        }
      }
      gbar(++seq);
    }
    if (exit_all) break;

    // ======== phase C : accept/reject + FSAL + next-step scal ========
    {
      const float t = tcur, dtv = scal[1];
      float k7v = 0.f;
      if (tid < NH) {
        int h = tid;
        float k1 = __ldcg(&g_k[0][bid*NH+h]);
        float k3 = __ldcg(&g_k[2][bid*NH+h]);
        float k4 = __ldcg(&g_k[3][bid*NH+h]);
        float k5 = __ldcg(&g_k[4][bid*NH+h]);
        float k6 = __ldcg(&g_k[5][bid*NH+h]);
        float k7 = __ldcg(&g_k[6][bid*NH+h]);
        k7v = k7;
        float ev = dt_c * (E0*k1 + E2*k3 + E3*k4 + E4*k5 + E5*k6 + E6*k7);
        float sc = 1e-3f + 1e-3f * fmaxf(fabsf(yreg), fabsf(ynew_r));
        float e = ev / sc;
        float e2v = e*e;
        #pragma unroll
        for (int o = 16; o > 0; o >>= 1) e2v += __shfl_down_sync(0xffffffffu, e2v, o);
        if ((tid & 31) == 0) red[tid >> 5] = e2v;
      }
      __syncthreads();
      if (tid == 0) {
        float ssum = red[0] + red[1] + red[2] + red[3];
        float err = sqrtf(ssum * (1.f/(float)NH));
        bool accept = (err <= 1.0f);
        float fac = 0.9f * powf(fmaxf(err, 1e-9f), -0.2f);
        fac = fminf(fmaxf(fac, 0.2f), 10.f);
        bool done = (t >= tEnd - 1e-8f);
        bool adv = accept && !done;
        float t_new = adv ? (t + dt_c) : t;
        float dt_new = done ? dtv : (dt_c * fac);
        scal[0] = t_new;
        scal[1] = dt_new;
        scal[2] = fminf(dt_new, tEnd - t_new);
        scal[3] = adv ? 1.f : 0.f;
        if (!counted && t_new >= tEnd - 1e-8f) {
          atomicAdd(&g_ndone, 1u);
          counted = true;
        }
      }
      __syncthreads();
      if (tid < NH && scal[3] != 0.f) {
        yreg = ynew_r;
        Ycur[tid] = ynew_r;
        __stcg(&g_k[0][bid*NH + tid], k7v);   // FSAL
      }
      __syncthreads();
    }
  }

  if (tid < NO) {
    float acc = lin_b[tid];
    #pragma unroll 4
    for (int h = 0; h < NH; h++)
      acc = fmaf(lin_w[tid*NH + h], Ycur[h], acc);
    out[bid*NO + tid] = acc;
  }
}

extern "C" void kernel_launch(void* const* d_in, const int* in_sizes, int n_in,
                              void* d_out, int out_size) {
  const float* ts    = (const float*)d_in[0];
  const float* xs    = (const float*)d_in[1];
  const float* W1    = (const float*)d_in[2];
  const float* b1    = (const float*)d_in[3];
  const float* W2    = (const float*)d_in[4];
  const float* b2    = (const float*)d_in[5];
  const float* lin_w = (const float*)d_in[6];
  const float* lin_b = (const float*)d_in[7];
  float* out = (float*)d_out;
  cudaFuncSetAttribute(cde_kernel, cudaFuncAttributeMaxDynamicSharedMemorySize, SMEM_BYTES);
  cde_kernel<<<NCTA, NTHR, SMEM_BYTES>>>(ts, xs, W1, b1, W2, b2, lin_w, lin_b, out);
}

// round 13
// speedup vs baseline: 55.0774x; 1.0244x over previous
#include <cuda_runtime.h>
#include <cuda_bf16.h>
#include <cstdint>

#define NB 128
#define NT 128
#define NC 32
#define NH 128
#define NO 10
#define NCTA 128
#define NTHR 256
#define MAXSTEPS 64

#define W1PR 132
#define W2PR 68
#define H1PR 68
#define DXPR 36
#define OFF_W1S 0
#define OFF_W2HI 16896
#define OFF_W2LO 19072
#define OFF_H1HI 21248
#define OFF_H1LO 29952
#define OFF_DXS 38656
#define OFF_RED 43264
#define OFF_TS  43520
#define OFF_B1  43648
#define OFF_B2  43776
#define OFF_YS  43808
#define OFF_YC  43936
#define OFF_SC  44064
#define SMEM_FLOATS 44072
#define SMEM_BYTES (SMEM_FLOATS * 4)

__device__ __align__(16) float g_k[7][NB*NH];
__device__ __align__(16) unsigned g_H1hi[NB*64];
__device__ __align__(16) unsigned g_H1lo[NB*64];
__device__ __align__(16) float g_dX[7][NB*NC];
__device__ __align__(128) unsigned g_flags[NCTA*32];
__device__ unsigned g_ndone;

__constant__ float A_TAB[7][6] = {
  {0.f,0.f,0.f,0.f,0.f,0.f},
  {(float)(1.0/5.0),0.f,0.f,0.f,0.f,0.f},
  {(float)(3.0/40.0),(float)(9.0/40.0),0.f,0.f,0.f,0.f},
  {(float)(44.0/45.0),(float)(-56.0/15.0),(float)(32.0/9.0),0.f,0.f,0.f},
  {(float)(19372.0/6561.0),(float)(-25360.0/2187.0),(float)(64448.0/6561.0),(float)(-212.0/729.0),0.f,0.f},
  {(float)(9017.0/3168.0),(float)(-355.0/33.0),(float)(46732.0/5247.0),(float)(49.0/176.0),(float)(-5103.0/18656.0),0.f},
  {(float)(35.0/384.0),0.f,(float)(500.0/1113.0),(float)(125.0/192.0),(float)(-2187.0/6784.0),(float)(11.0/84.0)},
};
__constant__ float C_TAB[7] = {0.f,(float)(1.0/5.0),(float)(3.0/10.0),(float)(4.0/5.0),(float)(8.0/9.0),1.f,1.f};

#define E0 ((float)(71.0/57600.0))
#define E2 ((float)(-71.0/16695.0))
#define E3 ((float)(71.0/1920.0))
#define E4 ((float)(-17253.0/339200.0))
#define E5 ((float)(22.0/525.0))
#define E6 ((float)(-1.0/40.0))

__device__ __forceinline__ unsigned ld_u32_cg(const unsigned* p) {
  unsigned v; asm volatile("ld.global.cg.u32 %0, [%1];" : "=r"(v) : "l"(p)); return v;
}
__device__ __forceinline__ unsigned ld_acq(const unsigned* p) {
  unsigned v; asm volatile("ld.acquire.gpu.global.u32 %0, [%1];" : "=r"(v) : "l"(p)); return v;
}
__device__ __forceinline__ void st_u32_cg(unsigned* p, unsigned v) {
  asm volatile("st.global.cg.u32 [%0], %1;" :: "l"(p), "r"(v) : "memory");
}
__device__ __forceinline__ float fast_tanh(float x) {
  x = fminf(fmaxf(x, -9.f), 9.f);
  float e = __expf(2.f * x);
  return __fdividef(e - 1.f, e + 1.f);
}
__device__ __forceinline__ uint32_t pack_bf16x2(float e0, float e1) {
  uint32_t d;
  asm("cvt.rn.bf16x2.f32 %0, %1, %2;" : "=r"(d) : "f"(e1), "f"(e0));
  return d;
}
__device__ __forceinline__ uint32_t smem_u32(const void* p) {
  uint32_t a;
  asm("{ .reg .u64 t; cvta.to.shared.u64 t, %1; cvt.u32.u64 %0, t; }" : "=r"(a) : "l"(p));
  return a;
}
__device__ __forceinline__ void mma_bf16(float* d, uint32_t a0, uint32_t a1, uint32_t a2, uint32_t a3,
                                         uint32_t b0, uint32_t b1) {
  asm volatile(
    "mma.sync.aligned.m16n8k16.row.col.f32.bf16.bf16.f32 "
    "{%0,%1,%2,%3}, {%4,%5,%6,%7}, {%8,%9}, {%0,%1,%2,%3};"
    : "+f"(d[0]), "+f"(d[1]), "+f"(d[2]), "+f"(d[3])
    : "r"(a0), "r"(a1), "r"(a2), "r"(a3), "r"(b0), "r"(b1));
}
__device__ __forceinline__ void ldmx4(uint32_t* r, uint32_t addr) {
  asm volatile("ldmatrix.sync.aligned.m8n8.x4.shared.b16 {%0,%1,%2,%3}, [%4];"
    : "=r"(r[0]), "=r"(r[1]), "=r"(r[2]), "=r"(r[3]) : "r"(addr));
}

// all-poll distributed barrier (monotone seq, replay-safe)
__device__ __forceinline__ void gbar(unsigned seq) {
  __syncthreads();
  const int tid = threadIdx.x;
  if (tid == 0) {
    __threadfence();
    st_u32_cg(&g_flags[blockIdx.x * 32], seq);
  }
  if (tid < NCTA) {
    while ((int)(ld_acq(&g_flags[tid * 32]) - seq) < 0) { }
  }
  __syncthreads();
}

__global__ __launch_bounds__(NTHR, 1)
void cde_kernel(const float* __restrict__ ts, const float* __restrict__ xs,
                const float* __restrict__ W1, const float* __restrict__ b1,
                const float* __restrict__ W2, const float* __restrict__ b2,
                const float* __restrict__ lin_w, const float* __restrict__ lin_b,
                float* __restrict__ out)
{
  extern __shared__ float sm[];
  float*    W1s  = sm + OFF_W1S;
  unsigned* W2hiS= (unsigned*)(sm + OFF_W2HI);
  unsigned* W2loS= (unsigned*)(sm + OFF_W2LO);
  unsigned* H1hiS= (unsigned*)(sm + OFF_H1HI);
  unsigned* H1loS= (unsigned*)(sm + OFF_H1LO);
  float*    dXs  = sm + OFF_DXS;
  float*    red  = sm + OFF_RED;
  float*    tss  = sm + OFF_TS;
  float*    b1s  = sm + OFF_B1;
  float*    b2s  = sm + OFF_B2;
  float*    Ysm  = sm + OFF_YS;
  float*    Ycur = sm + OFF_YC;
  float*    scal = sm + OFF_SC;

  const int tid = threadIdx.x;
  const int bid = blockIdx.x;
  const int wid = tid >> 5;
  const int lane = tid & 31;
  const int g = lane >> 2;
  const int q = lane & 3;
  const uint32_t smb = smem_u32(sm);

  const unsigned base_nd = ld_u32_cg(&g_ndone);
  unsigned seq = ld_u32_cg(&g_flags[bid * 32]);

  for (int i = tid; i < NH*NH; i += NTHR) { int h = i >> 7, k = i & 127; W1s[h*W1PR + k] = W1[i]; }
  for (int i = tid; i < 32*64; i += NTHR) {
    int c = i >> 6, kq = i & 63;
    float w0 = W2[bid*32*NH + c*NH + kq*2];
    float w1 = W2[bid*32*NH + c*NH + kq*2 + 1];
    __nv_bfloat16 h0 = __float2bfloat16(w0), h1 = __float2bfloat16(w1);
    W2hiS[c*W2PR + kq] = pack_bf16x2(w0, w1);
    W2loS[c*W2PR + kq] = pack_bf16x2(w0 - __bfloat162float(h0), w1 - __bfloat162float(h1));
  }
  for (int i = tid; i < NT; i += NTHR) tss[i] = ts[i];
  for (int i = tid; i < NH; i += NTHR) b1s[i] = b1[i];
  if (tid < 32) b2s[tid] = b2[bid*32 + tid];
  if (tid < NH) Ycur[tid] = 0.f;
  if (tid == 0) {
    float t0 = ts[0], te = ts[NT-1];
    scal[0] = t0; scal[1] = 0.01f; scal[2] = fminf(0.01f, te - t0);
  }
  __syncthreads();
  const float tEnd = tss[NT-1];
  const float* xb = xs + (size_t)bid*NT*NC;

  const int lrow = wid*16 + (lane & 7) + ((lane >> 3) & 1) * 8;
  const int lcol = ((lane >> 4) & 1) * 4;
  const uint32_t hibase = smb + (uint32_t)(OFF_H1HI + lrow*H1PR + lcol) * 4u;
  const uint32_t lobase = smb + (uint32_t)(OFF_H1LO + lrow*H1PR + lcol) * 4u;

  float yreg = 0.f;
  float ynew_r = 0.f;
  bool counted = false;
  bool exit_all = false;

  for (int step = 0; step < MAXSTEPS && !exit_all; step++) {
    const int sb = (step == 0) ? 0 : 1;   // FSAL
    const float tcur = scal[0];
    const float dt_c = scal[2];
    for (int s = sb; s < 7; s++) {
      // ======== phase A : CTA = batch ========
      if (s > sb) {
        for (int i = tid; i < (NB*NC)/4; i += NTHR) {
          int b = i >> 3, c4 = (i & 7) * 4;
          float4 u = __ldcg((const float4*)&g_dX[s][b*NC + c4]);
          *(float4*)&dXs[b*DXPR + c4] = u;
        }
      }
      if (tid < NH) {
        float ysv;
        if (s == 0) ysv = yreg;
        else {
          // unrolled predicated gather: 6 independent L2 loads (MLP=6)
          float kv[6];
          #pragma unroll
          for (int j = 0; j < 6; j++)
            kv[j] = (j < s) ? __ldcg(&g_k[j][bid*NH + tid]) : 0.f;
          float acc = A_TAB[s][0] * kv[0];
          #pragma unroll
          for (int j = 1; j < 6; j++)
            acc = fmaf(A_TAB[s][j], kv[j], acc);
          ysv = yreg + dt_c * acc;
        }
        Ysm[tid] = ysv;
        if (s == 6) ynew_r = ysv;
      } else if (s == sb) {
        for (int i = tid - 128; i < (7 - sb) * NC; i += 128) {
          int sp = sb + i / NC;
          int c = i % NC;
          float tq = tcur + C_TAB[sp] * dt_c;
          int lo = 0, hi = NT;
          while (lo < hi) { int mid = (lo + hi) >> 1; if (tss[mid] <= tq) lo = mid + 1; else hi = mid; }
          int idx = lo - 1; if (idx < 0) idx = 0; if (idx > NT-2) idx = NT-2;
          float t0 = tss[idx], t1 = tss[idx+1];
          float hh = t1 - t0;
          float sfr = (tq - t0) / hh;
          float dh00 = 6.f*sfr*sfr - 6.f*sfr;
          float dh10 = 3.f*sfr*sfr - 4.f*sfr + 1.f;
          float dh11 = 3.f*sfr*sfr - 2.f*sfr;
          float x0 = __ldg(&xb[idx*NC + c]);
          float x1 = __ldg(&xb[(idx+1)*NC + c]);
          float mi1 = (x1 - x0) / hh;
          float mi;
          if (idx == 0) mi = (x1 - x0) / (tss[1] - tss[0]);
          else { float xm1 = __ldg(&xb[(idx-1)*NC + c]); mi = (x0 - xm1) / (tss[idx] - tss[idx-1]); }
          float dx = (dh00*x0 - dh00*x1) / hh + dh10*mi + dh11*mi1;
          __stcg(&g_dX[sp][bid*NC + c], dx);
        }
      }
      __syncthreads();
      {
        int h = tid & 127;
        int half = tid >> 7;
        const int kb = half * 64;
        float a0=0.f,a1=0.f,a2=0.f,a3=0.f;
        const float* wrow = &W1s[h*W1PR + kb];
        #pragma unroll 4
        for (int k = 0; k < 64; k += 4) {
          float4 wv = *(const float4*)&wrow[k];
          float4 yv = *(const float4*)&Ysm[kb + k];
          a0 = fmaf(wv.x, yv.x, a0);
          a1 = fmaf(wv.y, yv.y, a1);
          a2 = fmaf(wv.z, yv.z, a2);
          a3 = fmaf(wv.w, yv.w, a3);
        }
        red[half*NH + h] = (a0+a1)+(a2+a3);
      }
      __syncthreads();
      if (tid < 64) {
        float f0 = fmaxf(b1s[2*tid]   + red[2*tid]   + red[NH + 2*tid],   0.f);
        float f1 = fmaxf(b1s[2*tid+1] + red[2*tid+1] + red[NH + 2*tid+1], 0.f);
        uint32_t hi = pack_bf16x2(f0, f1);
        __nv_bfloat162 hb = *reinterpret_cast<__nv_bfloat162*>(&hi);
        uint32_t lo = pack_bf16x2(f0 - __bfloat162float(hb.x), f1 - __bfloat162float(hb.y));
        st_u32_cg(&g_H1hi[bid*64 + tid], hi);
        st_u32_cg(&g_H1lo[bid*64 + tid], lo);
      }
      gbar(++seq);

      if (s == sb) {
        if (tid == 0) scal[4] = (float)(ld_u32_cg(&g_ndone) - base_nd);
        __syncthreads();
        if (scal[4] == (float)NB) { exit_all = true; break; }
      }

      // ======== phase B : CTA = h, ldmatrix + bf16 HMMA ========
      {
        for (int i = tid; i < 128*16; i += NTHR) {
          int row = i >> 4, c4 = (i & 15) * 4;
          uint4 u = __ldcg((const uint4*)&g_H1hi[row*64 + c4]);
          *(uint4*)&H1hiS[row*H1PR + c4] = u;
          uint4 v = __ldcg((const uint4*)&g_H1lo[row*64 + c4]);
          *(uint4*)&H1loS[row*H1PR + c4] = v;
        }
        if (s == sb) {
          for (int i = tid; i < (NB*NC)/4; i += NTHR) {
            int b = i >> 3, c4 = (i & 7) * 4;
            float4 u = __ldcg((const float4*)&g_dX[s][b*NC + c4]);
            *(float4*)&dXs[b*DXPR + c4] = u;
          }
        }
        __syncthreads();

        const int mb = wid * 16;
        float d[4][4];
        #pragma unroll
        for (int nt = 0; nt < 4; nt++)
          #pragma unroll
          for (int r = 0; r < 4; r++) d[nt][r] = 0.f;

        #pragma unroll
        for (int kk = 0; kk < 8; kk++) {
          const int kq = kk*8 + q;
          uint32_t ah[4], al[4];
          ldmx4(ah, hibase + (uint32_t)kk * 32u);
          ldmx4(al, lobase + (uint32_t)kk * 32u);
          #pragma unroll
          for (int nt = 0; nt < 4; nt++) {
            const int c = nt*8 + g;
            uint32_t bh0 = W2hiS[c*W2PR + kq];
            uint32_t bh1 = W2hiS[c*W2PR + kq + 4];
            uint32_t bl0 = W2loS[c*W2PR + kq];
            uint32_t bl1 = W2loS[c*W2PR + kq + 4];
            mma_bf16(d[nt], ah[0], ah[1], ah[2], ah[3], bh0, bh1);
            mma_bf16(d[nt], al[0], al[1], al[2], al[3], bh0, bh1);
            mma_bf16(d[nt], ah[0], ah[1], ah[2], ah[3], bl0, bl1);
          }
        }

        float part0 = 0.f, part1 = 0.f;
        const int row0 = mb + g, row1 = mb + g + 8;
        #pragma unroll
        for (int nt = 0; nt < 4; nt++) {
          const int cb = nt*8 + q*2;
          float bb0 = b2s[cb], bb1 = b2s[cb+1];
          part0 += fast_tanh(d[nt][0] + bb0) * dXs[row0*DXPR + cb]
                 + fast_tanh(d[nt][1] + bb1) * dXs[row0*DXPR + cb + 1];
          part1 += fast_tanh(d[nt][2] + bb0) * dXs[row1*DXPR + cb]
                 + fast_tanh(d[nt][3] + bb1) * dXs[row1*DXPR + cb + 1];
        }
        part0 += __shfl_xor_sync(0xffffffffu, part0, 1);
        part0 += __shfl_xor_sync(0xffffffffu, part0, 2);
        part1 += __shfl_xor_sync(0xffffffffu, part1, 1);
        part1 += __shfl_xor_sync(0xffffffffu, part1, 2);
        if (q == 0) {
          __stcg(&g_k[s][row0*NH + bid], part0);
          __stcg(&g_k[s][row1*NH + bid], part1);
        }
      }
      gbar(++seq);
    }
    if (exit_all) break;

    // ======== phase C : accept/reject + FSAL + next-step scal ========
    {
      const float t = tcur, dtv = scal[1];
      float k7v = 0.f;
      if (tid < NH) {
        int h = tid;
        float k1 = __ldcg(&g_k[0][bid*NH+h]);
        float k3 = __ldcg(&g_k[2][bid*NH+h]);
        float k4 = __ldcg(&g_k[3][bid*NH+h]);
        float k5 = __ldcg(&g_k[4][bid*NH+h]);
        float k6 = __ldcg(&g_k[5][bid*NH+h]);
        float k7 = __ldcg(&g_k[6][bid*NH+h]);
        k7v = k7;
        float ev = dt_c * (E0*k1 + E2*k3 + E3*k4 + E4*k5 + E5*k6 + E6*k7);
        float sc = 1e-3f + 1e-3f * fmaxf(fabsf(yreg), fabsf(ynew_r));
        float e = ev / sc;
        float e2v = e*e;
        #pragma unroll
        for (int o = 16; o > 0; o >>= 1) e2v += __shfl_down_sync(0xffffffffu, e2v, o);
        if ((tid & 31) == 0) red[tid >> 5] = e2v;
      }
      __syncthreads();
      if (tid == 0) {
        float ssum = red[0] + red[1] + red[2] + red[3];
        float err = sqrtf(ssum * (1.f/(float)NH));
        bool accept = (err <= 1.0f);
        float fac = 0.9f * powf(fmaxf(err, 1e-9f), -0.2f);
        fac = fminf(fmaxf(fac, 0.2f), 10.f);
        bool done = (t >= tEnd - 1e-8f);
        bool adv = accept && !done;
        float t_new = adv ? (t + dt_c) : t;
        float dt_new = done ? dtv : (dt_c * fac);
        scal[0] = t_new;
        scal[1] = dt_new;
        scal[2] = fminf(dt_new, tEnd - t_new);
        scal[3] = adv ? 1.f : 0.f;
        if (!counted && t_new >= tEnd - 1e-8f) {
          atomicAdd(&g_ndone, 1u);
          counted = true;
        }
      }
      __syncthreads();
      if (tid < NH && scal[3] != 0.f) {
        yreg = ynew_r;
        Ycur[tid] = ynew_r;
        __stcg(&g_k[0][bid*NH + tid], k7v);   // FSAL
      }
      __syncthreads();
    }
  }

  if (tid < NO) {
    float acc = lin_b[tid];
    #pragma unroll 4
    for (int h = 0; h < NH; h++)
      acc = fmaf(lin_w[tid*NH + h], Ycur[h], acc);
    out[bid*NO + tid] = acc;
  }
}

extern "C" void kernel_launch(void* const* d_in, const int* in_sizes, int n_in,
                              void* d_out, int out_size) {
  const float* ts    = (const float*)d_in[0];
  const float* xs    = (const float*)d_in[1];
  const float* W1    = (const float*)d_in[2];
  const float* b1    = (const float*)d_in[3];
  const float* W2    = (const float*)d_in[4];
  const float* b2    = (const float*)d_in[5];
  const float* lin_w = (const float*)d_in[6];
  const float* lin_b = (const float*)d_in[7];
  float* out = (float*)d_out;
  cudaFuncSetAttribute(cde_kernel, cudaFuncAttributeMaxDynamicSharedMemorySize, SMEM_BYTES);
  cde_kernel<<<NCTA, NTHR, SMEM_BYTES>>>(ts, xs, W1, b1, W2, b2, lin_w, lin_b, out);
}